// round 2
// baseline (speedup 1.0000x reference)
#include <cuda_runtime.h>
#include <cstdint>
#include <cstddef>

// GAT: N=4096, IN=128, OUT=256 (4 heads x 64), HID=256, slope=0.2
// K1 embed -> K1b score packs -> K2 fused masked-softmax attention -> K3 MLP+partial pool -> K4 decoder

#define NN 4096

__device__ float d_g[NN * 256];
__device__ float d_lpack[NN * 12];   // per node: sl[4], exp(sl)[4], exp(0.2*sl)[4]
__device__ float d_rpack[NN * 12];   // per node: sr[4], exp(sr)[4], exp(0.2*sr)[4]
__device__ float d_hatt[NN * 256];
__device__ float d_part[128 * 256];

typedef unsigned long long ull;

__device__ __forceinline__ ull pack2(float x) {
    ull r; asm("mov.b64 %0, {%1, %1};" : "=l"(r) : "f"(x)); return r;
}
__device__ __forceinline__ ull fma2(ull a, ull b, ull c) {
    ull d; asm("fma.rn.f32x2 %0, %1, %2, %3;" : "=l"(d) : "l"(a), "l"(b), "l"(c)); return d;
}
__device__ __forceinline__ float2 unpack2(ull v) {
    float2 r; asm("mov.b64 {%0, %1}, %2;" : "=f"(r.x), "=f"(r.y) : "l"(v)); return r;
}
__device__ __forceinline__ void cpa16(float* dst, const float* src) {
    unsigned s = (unsigned)__cvta_generic_to_shared(dst);
    asm volatile("cp.async.cg.shared.global [%0], [%1], 16;" ::"r"(s), "l"(src));
}

// ---------------- K1: g = nodes @ W_emb.T ----------------
__global__ __launch_bounds__(256) void k_embed(const float* __restrict__ nodes,
                                               const float* __restrict__ Wemb) {
    __shared__ float sA[32 * 128];
    const int tid = threadIdx.x, bi = blockIdx.x;
    const float4* src = (const float4*)(nodes + (size_t)bi * 4096);
    for (int k = tid; k < 1024; k += 256) ((float4*)sA)[k] = src[k];
    __syncthreads();
    const int o = tid;
    ull acc[32];
#pragma unroll
    for (int r = 0; r < 32; r++) acc[r] = 0ull;
    const float* wrow = Wemb + o * 128;
#pragma unroll 2
    for (int k = 0; k < 128; k += 2) {
        ull w2 = *(const ull*)(wrow + k);
#pragma unroll
        for (int r = 0; r < 32; r++)
            acc[r] = fma2(w2, *(const ull*)(sA + r * 128 + k), acc[r]);
    }
#pragma unroll
    for (int r = 0; r < 32; r++) {
        float2 u = unpack2(acc[r]);
        d_g[(size_t)(bi * 32 + r) * 256 + o] = u.x + u.y;
    }
}

// ---------------- K1b: per-(node,head) score packs ----------------
__global__ __launch_bounds__(256) void k_scores(const float* __restrict__ Watt) {
    const int t = blockIdx.x * 256 + threadIdx.x;  // 16384 total
    const int node = t >> 2, h = t & 3;
    const float* grow = d_g + (size_t)node * 256 + h * 64;
    float sl = 0.f, sr = 0.f;
#pragma unroll 8
    for (int k = 0; k < 64; k++) {
        float v = grow[k];
        sl += v * __ldg(Watt + k);
        sr += v * __ldg(Watt + 64 + k);
    }
    d_lpack[node * 12 + h] = sl;
    d_lpack[node * 12 + 4 + h] = expf(sl);
    d_lpack[node * 12 + 8 + h] = expf(0.2f * sl);
    d_rpack[node * 12 + h] = sr;
    d_rpack[node * 12 + 4 + h] = expf(sr);
    d_rpack[node * 12 + 8 + h] = expf(0.2f * sr);
}

// ---------------- K2: fused masked-softmax attention aggregation ----------------
// dyn smem floats: sg 2*8192 | rp 2*384 | wbuf 4096 | denomp 256 | invd 128  = 21632 f = 86528 B
#define SG_F 16384
#define RP_F 768
#define WB_F 4096
#define K2_SMEM 86528

__device__ __forceinline__ void issue_tile(int t, int buf, int tid, float* sg, float* rp) {
    const float* gsrc = d_g + (size_t)t * 8192;
    float* dst = sg + buf * 8192;
#pragma unroll
    for (int k = 0; k < 8; k++) { int c4 = (tid + k * 256) * 4; cpa16(dst + c4, gsrc + c4); }
    if (tid < 96) cpa16(rp + buf * 384 + tid * 4, d_rpack + (size_t)t * 384 + tid * 4);
}

__global__ __launch_bounds__(256, 1) void k_attn(const int* __restrict__ adj) {
    extern __shared__ float sm[];
    float* sg = sm;
    float* rp = sg + SG_F;
    float* wbuf = rp + RP_F;
    float* denomp = wbuf + WB_F;
    float* invd = denomp + 256;

    const int tid = threadIdx.x, bi = blockIdx.x;
    const int it = tid & 31, fgrp = tid >> 5;      // mainloop roles
    const int si = it, shd = fgrp & 3, sjh = fgrp >> 2;  // staging roles
    const int gi = bi * 32 + si;

    const float sl0 = d_lpack[gi * 12 + shd];
    const float e1l = d_lpack[gi * 12 + 4 + shd];
    const float e2l = d_lpack[gi * 12 + 8 + shd];
    float dsum = 0.f;

    ull acc[16];
#pragma unroll
    for (int q = 0; q < 16; q++) acc[q] = 0ull;

    const int4* arow = (const int4*)(adj + (size_t)gi * NN) + sjh * 4;
    int4 acur[4], anext[4];
#pragma unroll
    for (int q = 0; q < 4; q++) acur[q] = __ldg(arow + q);

    issue_tile(0, 0, tid, sg, rp);
    asm volatile("cp.async.commit_group;");

#pragma unroll 1
    for (int t = 0; t < 128; t++) {
        const int buf = t & 1;
        if (t < 127) {
            issue_tile(t + 1, buf ^ 1, tid, sg, rp);
            asm volatile("cp.async.commit_group;");
#pragma unroll
            for (int q = 0; q < 4; q++) anext[q] = __ldg(arow + (t + 1) * 8 + q);
            asm volatile("cp.async.wait_group 1;");
        } else {
            asm volatile("cp.async.wait_group 0;");
        }
        __syncthreads();  // tile t visible

        // stage weights for this tile: thread covers (si, shd, 16 j's)
        {
            const float* rpc = rp + buf * 384;
#pragma unroll
            for (int q = 0; q < 4; q++) {
                int av[4] = {acur[q].x, acur[q].y, acur[q].z, acur[q].w};
#pragma unroll
                for (int e = 0; e < 4; e++) {
                    int jj = sjh * 16 + q * 4 + e;
                    float srv = rpc[jj * 12 + shd];
                    float w = (sl0 + srv >= 0.f) ? e1l * rpc[jj * 12 + 4 + shd]
                                                 : e2l * rpc[jj * 12 + 8 + shd];
                    w = av[e] ? w : 0.f;
                    dsum += w;
                    wbuf[jj * 128 + shd * 32 + si] = w;
                }
            }
        }
        __syncthreads();  // weights ready

        // mainloop: thread (it, fgrp) does 4 heads x 8 f, packed f32x2
        {
            const float* sgc = sg + buf * 8192;
#pragma unroll 4
            for (int jj = 0; jj < 32; jj++) {
                const float* grow = sgc + jj * 256 + fgrp * 8;
                const float* wr = wbuf + jj * 128 + it;
#pragma unroll
                for (int h = 0; h < 4; h++) {
                    ull p = pack2(wr[h * 32]);
                    const double2* gp = (const double2*)(grow + h * 64);
                    double2 ga = gp[0], gb = gp[1];
                    acc[h * 4 + 0] = fma2(p, __double_as_longlong(ga.x), acc[h * 4 + 0]);
                    acc[h * 4 + 1] = fma2(p, __double_as_longlong(ga.y), acc[h * 4 + 1]);
                    acc[h * 4 + 2] = fma2(p, __double_as_longlong(gb.x), acc[h * 4 + 2]);
                    acc[h * 4 + 3] = fma2(p, __double_as_longlong(gb.y), acc[h * 4 + 3]);
                }
            }
        }
#pragma unroll
        for (int q = 0; q < 4; q++) acur[q] = anext[q];
        __syncthreads();  // protect wbuf + sg[buf^1] for next iter
    }

    // epilogue: denominators and scaled writeback
    denomp[(sjh * 4 + shd) * 32 + si] = dsum;
    __syncthreads();
    if (tid < 128) {
        int ii = tid & 31, hh = tid >> 5;
        invd[ii * 4 + hh] = 1.f / (denomp[hh * 32 + ii] + denomp[128 + hh * 32 + ii]);
    }
    __syncthreads();
    float* ob = d_hatt + (size_t)(bi * 32 + it) * 256 + fgrp * 8;
#pragma unroll
    for (int h = 0; h < 4; h++) {
        float s = invd[it * 4 + h];
#pragma unroll
        for (int q = 0; q < 2; q++) {
            float2 u0 = unpack2(acc[h * 4 + q * 2]);
            float2 u1 = unpack2(acc[h * 4 + q * 2 + 1]);
            *(float4*)(ob + h * 64 + q * 4) = make_float4(u0.x * s, u0.y * s, u1.x * s, u1.y * s);
        }
    }
}

// ---------------- K3: 2-layer MLP + per-block partial pooling ----------------
__global__ __launch_bounds__(256) void k_mlp(const float* __restrict__ We1, const float* __restrict__ b1,
                                             const float* __restrict__ We2, const float* __restrict__ b2) {
    extern __shared__ float sm[];
    float* sA = sm;          // 32 x 256
    float* sB = sm + 8192;   // 32 x 256
    const int tid = threadIdx.x, bi = blockIdx.x, o = tid;
    const float4* src = (const float4*)(d_hatt + (size_t)bi * 8192);
    for (int k = tid; k < 2048; k += 256) ((float4*)sA)[k] = src[k];
    __syncthreads();

    ull acc[32];
#pragma unroll
    for (int r = 0; r < 32; r++) acc[r] = 0ull;
    const float* wrow = We1 + o * 256;
#pragma unroll 2
    for (int k = 0; k < 256; k += 2) {
        ull w2 = *(const ull*)(wrow + k);
#pragma unroll
        for (int r = 0; r < 32; r++)
            acc[r] = fma2(w2, *(const ull*)(sA + r * 256 + k), acc[r]);
    }
    float bias = b1[o];
#pragma unroll
    for (int r = 0; r < 32; r++) {
        float2 u = unpack2(acc[r]);
        sB[r * 256 + o] = fmaxf(u.x + u.y + bias, 0.f);
    }
    __syncthreads();

#pragma unroll
    for (int r = 0; r < 32; r++) acc[r] = 0ull;
    wrow = We2 + o * 256;
#pragma unroll 2
    for (int k = 0; k < 256; k += 2) {
        ull w2 = *(const ull*)(wrow + k);
#pragma unroll
        for (int r = 0; r < 32; r++)
            acc[r] = fma2(w2, *(const ull*)(sB + r * 256 + k), acc[r]);
    }
    bias = b2[o];
    float p = 0.f;
#pragma unroll
    for (int r = 0; r < 32; r++) {
        float2 u = unpack2(acc[r]);
        p += u.x + u.y + bias;
    }
    d_part[bi * 256 + o] = p;
}

// ---------------- K4: pool + decoder ----------------
__global__ __launch_bounds__(256) void k_final(const float* __restrict__ Wd1, const float* __restrict__ bd1,
                                               const float* __restrict__ Wd2, const float* __restrict__ bd2,
                                               float* __restrict__ out) {
    __shared__ float pooled[256];
    __shared__ float red[256];
    const int o = threadIdx.x;
    float p = 0.f;
    for (int b = 0; b < 128; b++) p += d_part[b * 256 + o];
    pooled[o] = p;
    __syncthreads();
    float accv = 0.f;
    const float* w = Wd1 + o * 256;
#pragma unroll 4
    for (int k = 0; k < 256; k++) accv += w[k] * pooled[k];
    float z = fmaxf(accv + bd1[o], 0.f);
    red[o] = z * Wd2[o];
    __syncthreads();
    for (int s = 128; s > 0; s >>= 1) {
        if (o < s) red[o] += red[o + s];
        __syncthreads();
    }
    if (o == 0) out[0] = red[0] + bd2[0];
}

extern "C" void kernel_launch(void* const* d_in, const int* in_sizes, int n_in,
                              void* d_out, int out_size) {
    const float* nodes = (const float*)d_in[0];
    const int* adj = (const int*)d_in[1];
    const float* Wemb = (const float*)d_in[2];
    const float* Watt = (const float*)d_in[3];
    const float* We1 = (const float*)d_in[4];
    const float* b1 = (const float*)d_in[5];
    const float* We2 = (const float*)d_in[6];
    const float* b2 = (const float*)d_in[7];
    const float* Wd1 = (const float*)d_in[8];
    const float* bd1 = (const float*)d_in[9];
    const float* Wd2 = (const float*)d_in[10];
    const float* bd2 = (const float*)d_in[11];
    float* out = (float*)d_out;

    cudaFuncSetAttribute(k_attn, cudaFuncAttributeMaxDynamicSharedMemorySize, K2_SMEM);
    cudaFuncSetAttribute(k_mlp, cudaFuncAttributeMaxDynamicSharedMemorySize, 65536);

    k_embed<<<128, 256>>>(nodes, Wemb);
    k_scores<<<64, 256>>>(Watt);
    k_attn<<<128, 256, K2_SMEM>>>(adj);
    k_mlp<<<128, 256, 65536>>>(We1, b1, We2, b2);
    k_final<<<1, 256>>>(Wd1, bd1, Wd2, bd2, out);
}

// round 3
// speedup vs baseline: 1.1592x; 1.1592x over previous
#include <cuda_runtime.h>
#include <cstdint>
#include <cstddef>

// GAT N=4096, IN=128, OUT=256 (4 heads x 64), HID=256, slope=0.2
#define NN 4096

__device__ float d_g[NN * 256];
__device__ float d_lpack[NN * 12];     // per node: sl[4], exp(sl)[4], exp(0.2 sl)[4]
__device__ float4 d_rp4[NN * 4];       // per (node,h): {sr, exp(sr), exp(0.2 sr), 0}
__device__ float d_hattT[256 * NN];    // attention output, TRANSPOSED [feat][node]
__device__ float d_part[128 * 256];
__device__ float d_W1T[256 * 256];
__device__ float d_W2T[256 * 256];
__device__ float d_WembT[128 * 256];
__device__ float d_nodesT[128 * NN];

typedef unsigned long long ull;

__device__ __forceinline__ ull pack2(float x) {
    ull r; asm("mov.b64 %0, {%1, %1};" : "=l"(r) : "f"(x)); return r;
}
__device__ __forceinline__ ull fma2(ull a, ull b, ull c) {
    ull d; asm("fma.rn.f32x2 %0, %1, %2, %3;" : "=l"(d) : "l"(a), "l"(b), "l"(c)); return d;
}
__device__ __forceinline__ float2 unpack2(ull v) {
    float2 r; asm("mov.b64 {%0, %1}, %2;" : "=f"(r.x), "=f"(r.y) : "l"(v)); return r;
}
__device__ __forceinline__ ull dll(double v) { return __double_as_longlong(v); }
__device__ __forceinline__ void cpa16(float* dst, const float* src) {
    unsigned s = (unsigned)__cvta_generic_to_shared(dst);
    asm volatile("cp.async.cg.shared.global [%0], [%1], 16;" ::"r"(s), "l"(src));
}

// ---------------- prep: transposes of weights + nodes ----------------
__global__ __launch_bounds__(256) void k_prep(const float* __restrict__ We1,
                                              const float* __restrict__ We2,
                                              const float* __restrict__ Wemb,
                                              const float* __restrict__ nodes) {
    int i = blockIdx.x * 256 + threadIdx.x;  // 688128 total
    if (i < 65536) {
        int k = i >> 8, c = i & 255; d_W1T[i] = We1[c * 256 + k];
    } else if (i < 131072) {
        int j = i - 65536; int k = j >> 8, c = j & 255; d_W2T[j] = We2[c * 256 + k];
    } else if (i < 163840) {
        int j = i - 131072; int k = j >> 8, c = j & 255; d_WembT[j] = Wemb[c * 128 + k];
    } else {
        int j = i - 163840; int k = j >> 12, r = j & 4095; d_nodesT[j] = nodes[r * 128 + k];
    }
}

// ---------------- K1: g = nodes @ Wemb.T  (register-blocked 8x4) ----------------
__global__ __launch_bounds__(256) void k_embed() {
    const int tid = threadIdx.x, bi = blockIdx.x;
    const int fg = tid & 63, ig = tid >> 6;
    const int rowb = bi * 32 + ig * 8, colb = fg * 4;
    ull acc[16];
#pragma unroll
    for (int q = 0; q < 16; q++) acc[q] = 0ull;
#pragma unroll 2
    for (int k = 0; k < 128; k++) {
        double2 wd = *(const double2*)(d_WembT + k * 256 + colb);
        ull w01 = dll(wd.x), w23 = dll(wd.y);
        float4 a0 = *(const float4*)(d_nodesT + (size_t)k * 4096 + rowb);
        float4 a1 = *(const float4*)(d_nodesT + (size_t)k * 4096 + rowb + 4);
        float av[8] = {a0.x, a0.y, a0.z, a0.w, a1.x, a1.y, a1.z, a1.w};
#pragma unroll
        for (int r = 0; r < 8; r++) {
            ull p = pack2(av[r]);
            acc[r * 2] = fma2(p, w01, acc[r * 2]);
            acc[r * 2 + 1] = fma2(p, w23, acc[r * 2 + 1]);
        }
    }
#pragma unroll
    for (int r = 0; r < 8; r++) {
        float2 u0 = unpack2(acc[r * 2]), u1 = unpack2(acc[r * 2 + 1]);
        *(float4*)(d_g + (size_t)(rowb + r) * 256 + colb) = make_float4(u0.x, u0.y, u1.x, u1.y);
    }
}

// ---------------- K1b: score packs ----------------
__global__ __launch_bounds__(256) void k_scores(const float* __restrict__ Watt) {
    const int t = blockIdx.x * 256 + threadIdx.x;  // 16384
    const int node = t >> 2, h = t & 3;
    const float* grow = d_g + (size_t)node * 256 + h * 64;
    float sl = 0.f, sr = 0.f;
#pragma unroll 8
    for (int k = 0; k < 64; k++) {
        float v = grow[k];
        sl += v * __ldg(Watt + k);
        sr += v * __ldg(Watt + 64 + k);
    }
    d_lpack[node * 12 + h] = sl;
    d_lpack[node * 12 + 4 + h] = expf(sl);
    d_lpack[node * 12 + 8 + h] = expf(0.2f * sl);
    d_rp4[node * 4 + h] = make_float4(sr, expf(sr), expf(0.2f * sr), 0.f);
}

// ---------------- K2: fused masked-softmax attention ----------------
// smem: rp4 2*128 float4 (4KB) | sg 2*8192 f (64KB) | wbuf 4096 f (16KB) | denomp 256 | invd 128
#define K2_SMEM (4096 + 65536 + 16384 + 1024 + 512)

__device__ __forceinline__ void issue_tile(int t, int buf, int tid, float* sg, float4* rp4) {
    const float* gsrc = d_g + (size_t)t * 8192;
    float* dst = sg + buf * 8192;
#pragma unroll
    for (int kk = 0; kk < 8; kk++) {
        int L = tid + kk * 256;          // 16B chunk id, 0..2047
        int row = L >> 6, c4 = L & 63;
        int sw = c4 ^ ((c4 >> 3) & 7);   // bank-group swizzle
        cpa16(dst + row * 256 + sw * 4, gsrc + L * 4);
    }
    if (tid < 128) cpa16((float*)(rp4 + buf * 128 + tid), (const float*)(d_rp4 + t * 128 + tid));
}

__global__ __launch_bounds__(256, 1) void k_attn(const int* __restrict__ adj) {
    extern __shared__ char smraw[];
    float4* rp4 = (float4*)smraw;
    float* sg = (float*)(smraw + 4096);
    float* wbuf = (float*)(smraw + 4096 + 65536);
    float* denomp = wbuf + 4096;
    float* invd = denomp + 256;

    const int tid = threadIdx.x, bi = blockIdx.x;
    // mainloop roles
    const int fg = tid & 63, ig = tid >> 6;
    const int h = fg >> 4, r2b = ig * 2, colb = fg * 4;
    const int gsw = (fg ^ ((fg >> 3) & 7)) << 2;  // swizzled g float-offset
    // staging roles
    const int si = tid & 31, shd = (tid >> 5) & 3, sjh = tid >> 7;
    const int gi = bi * 32 + si;
    const float sl0 = d_lpack[gi * 12 + shd];
    const float e1l = d_lpack[gi * 12 + 4 + shd];
    const float e2l = d_lpack[gi * 12 + 8 + shd];
    float dsum = 0.f;

    ull acc[16];
#pragma unroll
    for (int q = 0; q < 16; q++) acc[q] = 0ull;

    const int4* arow = (const int4*)(adj + (size_t)gi * NN);
    int4 acur[4], anext[4];
#pragma unroll
    for (int q = 0; q < 4; q++) acur[q] = __ldg(arow + sjh * 4 + q);

    issue_tile(0, 0, tid, sg, rp4);
    asm volatile("cp.async.commit_group;");

#pragma unroll 1
    for (int t = 0; t < 128; t++) {
        const int buf = t & 1;
        asm volatile("cp.async.wait_group 0;");
        __syncthreads();  // tile t visible; prev mainloop done (safe to write wbuf)

        // ---- stage weights: thread covers (si, shd) x 16 j ----
        {
            const float4* rpc = rp4 + buf * 128;
#pragma unroll
            for (int q = 0; q < 4; q++) {
                int av[4] = {acur[q].x, acur[q].y, acur[q].z, acur[q].w};
#pragma unroll
                for (int e = 0; e < 4; e++) {
                    int jj = sjh * 16 + q * 4 + e;
                    float4 rv = rpc[jj * 4 + shd];
                    float w = (sl0 + rv.x >= 0.f) ? e1l * rv.y : e2l * rv.z;
                    w = av[e] ? w : 0.f;
                    dsum += w;
                    int blk = (jj * 32 + shd * 8 + (si >> 2)) ^ shd;
                    wbuf[blk * 4 + (si & 3)] = w;
                }
            }
        }
        __syncthreads();  // weights ready; prev staging read rp4[buf^1] done

        if (t < 127) {
            issue_tile(t + 1, buf ^ 1, tid, sg, rp4);
            asm volatile("cp.async.commit_group;");
#pragma unroll
            for (int q = 0; q < 4; q++) anext[q] = __ldg(arow + (t + 1) * 8 + sjh * 4 + q);
        }

        // ---- mainloop: 8 rows x 4 cols per thread, fma2 ----
        {
            const float* sgc = sg + buf * 8192;
#pragma unroll 4
            for (int jj = 0; jj < 32; jj++) {
                double2 gd = *(const double2*)(sgc + jj * 256 + gsw);
                ull g0 = dll(gd.x), g1 = dll(gd.y);
                int base = jj * 32 + h * 8 + r2b;
                float4 w0 = *(const float4*)(wbuf + ((base) ^ h) * 4);
                float4 w1 = *(const float4*)(wbuf + ((base + 1) ^ h) * 4);
                ull p;
                p = pack2(w0.x); acc[0] = fma2(p, g0, acc[0]);  acc[1] = fma2(p, g1, acc[1]);
                p = pack2(w0.y); acc[2] = fma2(p, g0, acc[2]);  acc[3] = fma2(p, g1, acc[3]);
                p = pack2(w0.z); acc[4] = fma2(p, g0, acc[4]);  acc[5] = fma2(p, g1, acc[5]);
                p = pack2(w0.w); acc[6] = fma2(p, g0, acc[6]);  acc[7] = fma2(p, g1, acc[7]);
                p = pack2(w1.x); acc[8] = fma2(p, g0, acc[8]);  acc[9] = fma2(p, g1, acc[9]);
                p = pack2(w1.y); acc[10] = fma2(p, g0, acc[10]); acc[11] = fma2(p, g1, acc[11]);
                p = pack2(w1.z); acc[12] = fma2(p, g0, acc[12]); acc[13] = fma2(p, g1, acc[13]);
                p = pack2(w1.w); acc[14] = fma2(p, g0, acc[14]); acc[15] = fma2(p, g1, acc[15]);
            }
        }
#pragma unroll
        for (int q = 0; q < 4; q++) acur[q] = anext[q];
    }

    // ---- epilogue: denominators, scale, transposed writeback ----
    denomp[(sjh * 4 + shd) * 32 + si] = dsum;
    __syncthreads();
    if (tid < 128) {
        int ii = tid & 31, hh = tid >> 5;
        invd[ii * 4 + hh] = 1.f / (denomp[hh * 32 + ii] + denomp[128 + hh * 32 + ii]);
    }
    __syncthreads();
    float z[8][4];
#pragma unroll
    for (int r = 0; r < 8; r++) {
        float s = invd[(ig * 8 + r) * 4 + h];
        float2 u0 = unpack2(acc[r * 2]), u1 = unpack2(acc[r * 2 + 1]);
        z[r][0] = u0.x * s; z[r][1] = u0.y * s; z[r][2] = u1.x * s; z[r][3] = u1.y * s;
    }
#pragma unroll
    for (int cc = 0; cc < 4; cc++) {
        size_t off = (size_t)(colb + cc) * 4096 + bi * 32 + ig * 8;
        *(float4*)(d_hattT + off) = make_float4(z[0][cc], z[1][cc], z[2][cc], z[3][cc]);
        *(float4*)(d_hattT + off + 4) = make_float4(z[4][cc], z[5][cc], z[6][cc], z[7][cc]);
    }
}

// ---------------- K3: 2-layer MLP + partial pool (register-blocked) ----------------
__global__ __launch_bounds__(256) void k_mlp(const float* __restrict__ b1,
                                             const float* __restrict__ b2) {
    __shared__ float sZT[8192];     // 256 k x 32 rows, XOR-swizzled 16B blocks
    __shared__ float sPart[1024];
    const int tid = threadIdx.x, bi = blockIdx.x;
    const int fg = tid & 63, ig = tid >> 6;
    const int rowb = bi * 32 + ig * 8, colb = fg * 4;

    ull acc[16];
#pragma unroll
    for (int q = 0; q < 16; q++) acc[q] = 0ull;
#pragma unroll 2
    for (int k = 0; k < 256; k++) {
        double2 wd = *(const double2*)(d_W1T + k * 256 + colb);
        ull w01 = dll(wd.x), w23 = dll(wd.y);
        float4 a0 = *(const float4*)(d_hattT + (size_t)k * 4096 + rowb);
        float4 a1 = *(const float4*)(d_hattT + (size_t)k * 4096 + rowb + 4);
        float av[8] = {a0.x, a0.y, a0.z, a0.w, a1.x, a1.y, a1.z, a1.w};
#pragma unroll
        for (int r = 0; r < 8; r++) {
            ull p = pack2(av[r]);
            acc[r * 2] = fma2(p, w01, acc[r * 2]);
            acc[r * 2 + 1] = fma2(p, w23, acc[r * 2 + 1]);
        }
    }
    float4 bb = *(const float4*)(b1 + colb);
    float zz[8][4];
#pragma unroll
    for (int r = 0; r < 8; r++) {
        float2 u0 = unpack2(acc[r * 2]), u1 = unpack2(acc[r * 2 + 1]);
        zz[r][0] = fmaxf(u0.x + bb.x, 0.f); zz[r][1] = fmaxf(u0.y + bb.y, 0.f);
        zz[r][2] = fmaxf(u1.x + bb.z, 0.f); zz[r][3] = fmaxf(u1.y + bb.w, 0.f);
    }
#pragma unroll
    for (int cc = 0; cc < 4; cc++) {
        int c = colb + cc, sw = (c >> 2) & 7;
        int blo = (c * 8 + ig * 2) ^ sw, bhi = (c * 8 + ig * 2 + 1) ^ sw;
        *(float4*)(sZT + blo * 4) = make_float4(zz[0][cc], zz[1][cc], zz[2][cc], zz[3][cc]);
        *(float4*)(sZT + bhi * 4) = make_float4(zz[4][cc], zz[5][cc], zz[6][cc], zz[7][cc]);
    }
    __syncthreads();

#pragma unroll
    for (int q = 0; q < 16; q++) acc[q] = 0ull;
#pragma unroll 2
    for (int k = 0; k < 256; k++) {
        double2 wd = *(const double2*)(d_W2T + k * 256 + colb);
        ull w01 = dll(wd.x), w23 = dll(wd.y);
        int sw = (k >> 2) & 7;
        float4 a0 = *(const float4*)(sZT + (((k * 8 + ig * 2)) ^ sw) * 4);
        float4 a1 = *(const float4*)(sZT + (((k * 8 + ig * 2 + 1)) ^ sw) * 4);
        float av[8] = {a0.x, a0.y, a0.z, a0.w, a1.x, a1.y, a1.z, a1.w};
#pragma unroll
        for (int r = 0; r < 8; r++) {
            ull p = pack2(av[r]);
            acc[r * 2] = fma2(p, w01, acc[r * 2]);
            acc[r * 2 + 1] = fma2(p, w23, acc[r * 2 + 1]);
        }
    }
    float4 b2v = *(const float4*)(b2 + colb);
    float pc0 = 8.f * b2v.x, pc1 = 8.f * b2v.y, pc2 = 8.f * b2v.z, pc3 = 8.f * b2v.w;
#pragma unroll
    for (int r = 0; r < 8; r++) {
        float2 u0 = unpack2(acc[r * 2]), u1 = unpack2(acc[r * 2 + 1]);
        pc0 += u0.x; pc1 += u0.y; pc2 += u1.x; pc3 += u1.y;
    }
    *(float4*)(sPart + ig * 256 + colb) = make_float4(pc0, pc1, pc2, pc3);
    __syncthreads();
    d_part[bi * 256 + tid] = sPart[tid] + sPart[256 + tid] + sPart[512 + tid] + sPart[768 + tid];
}

// ---------------- K4: pool + decoder ----------------
__global__ __launch_bounds__(256) void k_final(const float* __restrict__ Wd1, const float* __restrict__ bd1,
                                               const float* __restrict__ Wd2, const float* __restrict__ bd2,
                                               float* __restrict__ out) {
    __shared__ float pooled[256];
    __shared__ float red[256];
    const int o = threadIdx.x;
    float p = 0.f;
    for (int b = 0; b < 128; b++) p += d_part[b * 256 + o];
    pooled[o] = p;
    __syncthreads();
    float accv = 0.f;
    const float* w = Wd1 + o * 256;
#pragma unroll 4
    for (int k = 0; k < 256; k++) accv += w[k] * pooled[k];
    float zf = fmaxf(accv + bd1[o], 0.f);
    red[o] = zf * Wd2[o];
    __syncthreads();
    for (int s = 128; s > 0; s >>= 1) {
        if (o < s) red[o] += red[o + s];
        __syncthreads();
    }
    if (o == 0) out[0] = red[0] + bd2[0];
}

extern "C" void kernel_launch(void* const* d_in, const int* in_sizes, int n_in,
                              void* d_out, int out_size) {
    const float* nodes = (const float*)d_in[0];
    const int* adj = (const int*)d_in[1];
    const float* Wemb = (const float*)d_in[2];
    const float* Watt = (const float*)d_in[3];
    const float* We1 = (const float*)d_in[4];
    const float* b1 = (const float*)d_in[5];
    const float* We2 = (const float*)d_in[6];
    const float* b2 = (const float*)d_in[7];
    const float* Wd1 = (const float*)d_in[8];
    const float* bd1 = (const float*)d_in[9];
    const float* Wd2 = (const float*)d_in[10];
    const float* bd2 = (const float*)d_in[11];
    float* out = (float*)d_out;

    cudaFuncSetAttribute(k_attn, cudaFuncAttributeMaxDynamicSharedMemorySize, K2_SMEM);

    k_prep<<<2688, 256>>>(We1, We2, Wemb, nodes);
    k_embed<<<128, 256>>>();
    k_scores<<<64, 256>>>(Watt);
    k_attn<<<128, 256, K2_SMEM>>>(adj);
    k_mlp<<<128, 256>>>(b1, b2);
    k_final<<<1, 256>>>(Wd1, bd1, Wd2, bd2, out);
}

// round 4
// speedup vs baseline: 1.1614x; 1.0019x over previous
#include <cuda_runtime.h>
#include <cstdint>
#include <cstddef>

// GAT N=4096, IN=128, OUT=256 (4 heads x 64), HID=256, slope=0.2
#define NN 4096

__device__ float d_g[NN * 256];
__device__ float d_lpack[NN * 12];     // per node: sl[4], exp(sl)[4], exp(0.2 sl)[4]
__device__ float4 d_rp4[NN * 4];       // per (node,h): {sr, exp(sr), exp(0.2 sr), 0}
__device__ float d_hattT[256 * NN];    // attention output, TRANSPOSED [feat][node]
__device__ float d_part[128 * 256];
__device__ float d_W1T[256 * 256];
__device__ float d_W2T[256 * 256];
__device__ float d_WembT[128 * 256];
__device__ float d_nodesT[128 * NN];

typedef unsigned long long ull;

__device__ __forceinline__ ull pack2(float x) {
    ull r; asm("mov.b64 %0, {%1, %1};" : "=l"(r) : "f"(x)); return r;
}
__device__ __forceinline__ ull fma2(ull a, ull b, ull c) {
    ull d; asm("fma.rn.f32x2 %0, %1, %2, %3;" : "=l"(d) : "l"(a), "l"(b), "l"(c)); return d;
}
__device__ __forceinline__ float2 unpack2(ull v) {
    float2 r; asm("mov.b64 {%0, %1}, %2;" : "=f"(r.x), "=f"(r.y) : "l"(v)); return r;
}
__device__ __forceinline__ ull dll(double v) { return __double_as_longlong(v); }
__device__ __forceinline__ void cpa16(float* dst, const float* src) {
    unsigned s = (unsigned)__cvta_generic_to_shared(dst);
    asm volatile("cp.async.cg.shared.global [%0], [%1], 16;" ::"r"(s), "l"(src));
}

// ---------------- prep: transposes of weights + nodes ----------------
__global__ __launch_bounds__(256) void k_prep(const float* __restrict__ We1,
                                              const float* __restrict__ We2,
                                              const float* __restrict__ Wemb,
                                              const float* __restrict__ nodes) {
    int i = blockIdx.x * 256 + threadIdx.x;  // 688128 total
    if (i < 65536) {
        int k = i >> 8, c = i & 255; d_W1T[i] = We1[c * 256 + k];
    } else if (i < 131072) {
        int j = i - 65536; int k = j >> 8, c = j & 255; d_W2T[j] = We2[c * 256 + k];
    } else if (i < 163840) {
        int j = i - 131072; int k = j >> 8, c = j & 255; d_WembT[j] = Wemb[c * 128 + k];
    } else {
        int j = i - 163840; int k = j >> 12, r = j & 4095; d_nodesT[j] = nodes[r * 128 + k];
    }
}

// ---------------- K1: g = nodes @ Wemb.T  (register-blocked 8x4) ----------------
__global__ __launch_bounds__(256) void k_embed() {
    const int tid = threadIdx.x, bi = blockIdx.x;
    const int fg = tid & 63, ig = tid >> 6;
    const int rowb = bi * 32 + ig * 8, colb = fg * 4;
    ull acc[16];
#pragma unroll
    for (int q = 0; q < 16; q++) acc[q] = 0ull;
#pragma unroll 2
    for (int k = 0; k < 128; k++) {
        double2 wd = *(const double2*)(d_WembT + k * 256 + colb);
        ull w01 = dll(wd.x), w23 = dll(wd.y);
        float4 a0 = *(const float4*)(d_nodesT + (size_t)k * 4096 + rowb);
        float4 a1 = *(const float4*)(d_nodesT + (size_t)k * 4096 + rowb + 4);
        float av[8] = {a0.x, a0.y, a0.z, a0.w, a1.x, a1.y, a1.z, a1.w};
#pragma unroll
        for (int r = 0; r < 8; r++) {
            ull p = pack2(av[r]);
            acc[r * 2] = fma2(p, w01, acc[r * 2]);
            acc[r * 2 + 1] = fma2(p, w23, acc[r * 2 + 1]);
        }
    }
#pragma unroll
    for (int r = 0; r < 8; r++) {
        float2 u0 = unpack2(acc[r * 2]), u1 = unpack2(acc[r * 2 + 1]);
        *(float4*)(d_g + (size_t)(rowb + r) * 256 + colb) = make_float4(u0.x, u0.y, u1.x, u1.y);
    }
}

// ---------------- K1b: score packs ----------------
__global__ __launch_bounds__(256) void k_scores(const float* __restrict__ Watt) {
    const int t = blockIdx.x * 256 + threadIdx.x;  // 16384
    const int node = t >> 2, h = t & 3;
    const float* grow = d_g + (size_t)node * 256 + h * 64;
    float sl = 0.f, sr = 0.f;
#pragma unroll 8
    for (int k = 0; k < 64; k++) {
        float v = grow[k];
        sl += v * __ldg(Watt + k);
        sr += v * __ldg(Watt + 64 + k);
    }
    d_lpack[node * 12 + h] = sl;
    d_lpack[node * 12 + 4 + h] = expf(sl);
    d_lpack[node * 12 + 8 + h] = expf(0.2f * sl);
    d_rp4[node * 4 + h] = make_float4(sr, expf(sr), expf(0.2f * sr), 0.f);
}

// ---------------- K2: fused masked-softmax attention ----------------
// smem: rp4 2*128 float4 (4KB) | sg 2*8192 f (64KB) | wbuf 4096 f (16KB) | denomp 256 | invd 128
#define K2_SMEM (4096 + 65536 + 16384 + 1024 + 512)

__device__ __forceinline__ void issue_tile(int t, int buf, int tid, float* sg, float4* rp4) {
    const float* gsrc = d_g + (size_t)t * 8192;
    float* dst = sg + buf * 8192;
#pragma unroll
    for (int kk = 0; kk < 8; kk++) {
        int L = tid + kk * 256;          // 16B chunk id, 0..2047
        int row = L >> 6, c4 = L & 63;
        int sw = c4 ^ ((c4 >> 3) & 7);   // bank-group swizzle
        cpa16(dst + row * 256 + sw * 4, gsrc + L * 4);
    }
    if (tid < 128) cpa16((float*)(rp4 + buf * 128 + tid), (const float*)(d_rp4 + t * 128 + tid));
}

__global__ __launch_bounds__(256, 1) void k_attn(const int* __restrict__ adj) {
    extern __shared__ char smraw[];
    float4* rp4 = (float4*)smraw;
    float* sg = (float*)(smraw + 4096);
    float* wbuf = (float*)(smraw + 4096 + 65536);
    float* denomp = wbuf + 4096;
    float* invd = denomp + 256;

    const int tid = threadIdx.x, bi = blockIdx.x;
    // mainloop roles
    const int fg = tid & 63, ig = tid >> 6;
    const int h = fg >> 4, r2b = ig * 2, colb = fg * 4;
    const int gsw = (fg ^ ((fg >> 3) & 7)) << 2;  // swizzled g float-offset
    // staging roles
    const int si = tid & 31, shd = (tid >> 5) & 3, sjh = tid >> 7;
    const int gi = bi * 32 + si;
    const float sl0 = d_lpack[gi * 12 + shd];
    const float e1l = d_lpack[gi * 12 + 4 + shd];
    const float e2l = d_lpack[gi * 12 + 8 + shd];
    float dsum = 0.f;

    ull acc[16];
#pragma unroll
    for (int q = 0; q < 16; q++) acc[q] = 0ull;

    const int4* arow = (const int4*)(adj + (size_t)gi * NN);
    int4 acur[4], anext[4];
#pragma unroll
    for (int q = 0; q < 4; q++) acur[q] = __ldg(arow + sjh * 4 + q);

    issue_tile(0, 0, tid, sg, rp4);
    asm volatile("cp.async.commit_group;");

#pragma unroll 1
    for (int t = 0; t < 128; t++) {
        const int buf = t & 1;
        asm volatile("cp.async.wait_group 0;");
        __syncthreads();  // tile t visible; prev mainloop done (safe to write wbuf)

        // ---- stage weights: thread covers (si, shd) x 16 j ----
        {
            const float4* rpc = rp4 + buf * 128;
#pragma unroll
            for (int q = 0; q < 4; q++) {
                int av[4] = {acur[q].x, acur[q].y, acur[q].z, acur[q].w};
#pragma unroll
                for (int e = 0; e < 4; e++) {
                    int jj = sjh * 16 + q * 4 + e;
                    float4 rv = rpc[jj * 4 + shd];
                    float w = (sl0 + rv.x >= 0.f) ? e1l * rv.y : e2l * rv.z;
                    w = av[e] ? w : 0.f;
                    dsum += w;
                    int blk = (jj * 32 + shd * 8 + (si >> 2)) ^ shd;
                    wbuf[blk * 4 + (si & 3)] = w;
                }
            }
        }
        __syncthreads();  // weights ready; prev staging read rp4[buf^1] done

        if (t < 127) {
            issue_tile(t + 1, buf ^ 1, tid, sg, rp4);
            asm volatile("cp.async.commit_group;");
#pragma unroll
            for (int q = 0; q < 4; q++) anext[q] = __ldg(arow + (t + 1) * 8 + sjh * 4 + q);
        }

        // ---- mainloop: 8 rows x 4 cols per thread, fma2 ----
        {
            const float* sgc = sg + buf * 8192;
#pragma unroll 4
            for (int jj = 0; jj < 32; jj++) {
                double2 gd = *(const double2*)(sgc + jj * 256 + gsw);
                ull g0 = dll(gd.x), g1 = dll(gd.y);
                int base = jj * 32 + h * 8 + r2b;
                float4 w0 = *(const float4*)(wbuf + ((base) ^ h) * 4);
                float4 w1 = *(const float4*)(wbuf + ((base + 1) ^ h) * 4);
                ull p;
                p = pack2(w0.x); acc[0] = fma2(p, g0, acc[0]);  acc[1] = fma2(p, g1, acc[1]);
                p = pack2(w0.y); acc[2] = fma2(p, g0, acc[2]);  acc[3] = fma2(p, g1, acc[3]);
                p = pack2(w0.z); acc[4] = fma2(p, g0, acc[4]);  acc[5] = fma2(p, g1, acc[5]);
                p = pack2(w0.w); acc[6] = fma2(p, g0, acc[6]);  acc[7] = fma2(p, g1, acc[7]);
                p = pack2(w1.x); acc[8] = fma2(p, g0, acc[8]);  acc[9] = fma2(p, g1, acc[9]);
                p = pack2(w1.y); acc[10] = fma2(p, g0, acc[10]); acc[11] = fma2(p, g1, acc[11]);
                p = pack2(w1.z); acc[12] = fma2(p, g0, acc[12]); acc[13] = fma2(p, g1, acc[13]);
                p = pack2(w1.w); acc[14] = fma2(p, g0, acc[14]); acc[15] = fma2(p, g1, acc[15]);
            }
        }
#pragma unroll
        for (int q = 0; q < 4; q++) acur[q] = anext[q];
    }

    // ---- epilogue: denominators, scale, transposed writeback ----
    denomp[(sjh * 4 + shd) * 32 + si] = dsum;
    __syncthreads();
    if (tid < 128) {
        int ii = tid & 31, hh = tid >> 5;
        invd[ii * 4 + hh] = 1.f / (denomp[hh * 32 + ii] + denomp[128 + hh * 32 + ii]);
    }
    __syncthreads();
    float z[8][4];
#pragma unroll
    for (int r = 0; r < 8; r++) {
        float s = invd[(ig * 8 + r) * 4 + h];
        float2 u0 = unpack2(acc[r * 2]), u1 = unpack2(acc[r * 2 + 1]);
        z[r][0] = u0.x * s; z[r][1] = u0.y * s; z[r][2] = u1.x * s; z[r][3] = u1.y * s;
    }
#pragma unroll
    for (int cc = 0; cc < 4; cc++) {
        size_t off = (size_t)(colb + cc) * 4096 + bi * 32 + ig * 8;
        *(float4*)(d_hattT + off) = make_float4(z[0][cc], z[1][cc], z[2][cc], z[3][cc]);
        *(float4*)(d_hattT + off + 4) = make_float4(z[4][cc], z[5][cc], z[6][cc], z[7][cc]);
    }
}

// ---------------- K3: 2-layer MLP + partial pool (register-blocked) ----------------
__global__ __launch_bounds__(256) void k_mlp(const float* __restrict__ b1,
                                             const float* __restrict__ b2) {
    __shared__ float sZT[8192];     // 256 k x 32 rows, XOR-swizzled 16B blocks
    __shared__ float sPart[1024];
    const int tid = threadIdx.x, bi = blockIdx.x;
    const int fg = tid & 63, ig = tid >> 6;
    const int rowb = bi * 32 + ig * 8, colb = fg * 4;

    ull acc[16];
#pragma unroll
    for (int q = 0; q < 16; q++) acc[q] = 0ull;
#pragma unroll 2
    for (int k = 0; k < 256; k++) {
        double2 wd = *(const double2*)(d_W1T + k * 256 + colb);
        ull w01 = dll(wd.x), w23 = dll(wd.y);
        float4 a0 = *(const float4*)(d_hattT + (size_t)k * 4096 + rowb);
        float4 a1 = *(const float4*)(d_hattT + (size_t)k * 4096 + rowb + 4);
        float av[8] = {a0.x, a0.y, a0.z, a0.w, a1.x, a1.y, a1.z, a1.w};
#pragma unroll
        for (int r = 0; r < 8; r++) {
            ull p = pack2(av[r]);
            acc[r * 2] = fma2(p, w01, acc[r * 2]);
            acc[r * 2 + 1] = fma2(p, w23, acc[r * 2 + 1]);
        }
    }
    float4 bb = *(const float4*)(b1 + colb);
    float zz[8][4];
#pragma unroll
    for (int r = 0; r < 8; r++) {
        float2 u0 = unpack2(acc[r * 2]), u1 = unpack2(acc[r * 2 + 1]);
        zz[r][0] = fmaxf(u0.x + bb.x, 0.f); zz[r][1] = fmaxf(u0.y + bb.y, 0.f);
        zz[r][2] = fmaxf(u1.x + bb.z, 0.f); zz[r][3] = fmaxf(u1.y + bb.w, 0.f);
    }
#pragma unroll
    for (int cc = 0; cc < 4; cc++) {
        int c = colb + cc, sw = (c >> 2) & 7;
        int blo = (c * 8 + ig * 2) ^ sw, bhi = (c * 8 + ig * 2 + 1) ^ sw;
        *(float4*)(sZT + blo * 4) = make_float4(zz[0][cc], zz[1][cc], zz[2][cc], zz[3][cc]);
        *(float4*)(sZT + bhi * 4) = make_float4(zz[4][cc], zz[5][cc], zz[6][cc], zz[7][cc]);
    }
    __syncthreads();

#pragma unroll
    for (int q = 0; q < 16; q++) acc[q] = 0ull;
#pragma unroll 2
    for (int k = 0; k < 256; k++) {
        double2 wd = *(const double2*)(d_W2T + k * 256 + colb);
        ull w01 = dll(wd.x), w23 = dll(wd.y);
        int sw = (k >> 2) & 7;
        float4 a0 = *(const float4*)(sZT + (((k * 8 + ig * 2)) ^ sw) * 4);
        float4 a1 = *(const float4*)(sZT + (((k * 8 + ig * 2 + 1)) ^ sw) * 4);
        float av[8] = {a0.x, a0.y, a0.z, a0.w, a1.x, a1.y, a1.z, a1.w};
#pragma unroll
        for (int r = 0; r < 8; r++) {
            ull p = pack2(av[r]);
            acc[r * 2] = fma2(p, w01, acc[r * 2]);
            acc[r * 2 + 1] = fma2(p, w23, acc[r * 2 + 1]);
        }
    }
    float4 b2v = *(const float4*)(b2 + colb);
    float pc0 = 8.f * b2v.x, pc1 = 8.f * b2v.y, pc2 = 8.f * b2v.z, pc3 = 8.f * b2v.w;
#pragma unroll
    for (int r = 0; r < 8; r++) {
        float2 u0 = unpack2(acc[r * 2]), u1 = unpack2(acc[r * 2 + 1]);
        pc0 += u0.x; pc1 += u0.y; pc2 += u1.x; pc3 += u1.y;
    }
    *(float4*)(sPart + ig * 256 + colb) = make_float4(pc0, pc1, pc2, pc3);
    __syncthreads();
    d_part[bi * 256 + tid] = sPart[tid] + sPart[256 + tid] + sPart[512 + tid] + sPart[768 + tid];
}

// ---------------- K4: pool + decoder ----------------
__global__ __launch_bounds__(256) void k_final(const float* __restrict__ Wd1, const float* __restrict__ bd1,
                                               const float* __restrict__ Wd2, const float* __restrict__ bd2,
                                               float* __restrict__ out) {
    __shared__ float pooled[256];
    __shared__ float red[256];
    const int o = threadIdx.x;
    float p = 0.f;
    for (int b = 0; b < 128; b++) p += d_part[b * 256 + o];
    pooled[o] = p;
    __syncthreads();
    float accv = 0.f;
    const float* w = Wd1 + o * 256;
#pragma unroll 4
    for (int k = 0; k < 256; k++) accv += w[k] * pooled[k];
    float zf = fmaxf(accv + bd1[o], 0.f);
    red[o] = zf * Wd2[o];
    __syncthreads();
    for (int s = 128; s > 0; s >>= 1) {
        if (o < s) red[o] += red[o + s];
        __syncthreads();
    }
    if (o == 0) out[0] = red[0] + bd2[0];
}

extern "C" void kernel_launch(void* const* d_in, const int* in_sizes, int n_in,
                              void* d_out, int out_size) {
    const float* nodes = (const float*)d_in[0];
    const int* adj = (const int*)d_in[1];
    const float* Wemb = (const float*)d_in[2];
    const float* Watt = (const float*)d_in[3];
    const float* We1 = (const float*)d_in[4];
    const float* b1 = (const float*)d_in[5];
    const float* We2 = (const float*)d_in[6];
    const float* b2 = (const float*)d_in[7];
    const float* Wd1 = (const float*)d_in[8];
    const float* bd1 = (const float*)d_in[9];
    const float* Wd2 = (const float*)d_in[10];
    const float* bd2 = (const float*)d_in[11];
    float* out = (float*)d_out;

    cudaFuncSetAttribute(k_attn, cudaFuncAttributeMaxDynamicSharedMemorySize, K2_SMEM);

    k_prep<<<2688, 256>>>(We1, We2, Wemb, nodes);
    k_embed<<<128, 256>>>();
    k_scores<<<64, 256>>>(Watt);
    k_attn<<<128, 256, K2_SMEM>>>(adj);
    k_mlp<<<128, 256>>>(b1, b2);
    k_final<<<1, 256>>>(Wd1, bd1, Wd2, bd2, out);
}

// round 6
// speedup vs baseline: 2.2814x; 1.9643x over previous
#include <cuda_runtime.h>
#include <cstdint>
#include <cstddef>

#define NN 4096
typedef unsigned long long ull;
typedef unsigned int uint32;

__device__ float d_g[NN * 256];
__device__ unsigned short d_gbfT[256 * NN];  // bf16 g transposed [feat][node]
__device__ float d_lpack[NN * 12];
__device__ float4 d_rp4[NN * 4];             // {sr, exp(sr), exp(.2sr), 0}
__device__ unsigned d_adjT[128 * NN * 2];    // adjacency bits, tile-major: [(t*4096+node)*2+w]
__device__ float d_hattT[256 * NN];
__device__ float d_part[128 * 256];
__device__ float d_W1T[256 * 256];
__device__ float d_W2T[256 * 256];
__device__ float d_WembT[128 * 256];
__device__ float d_nodesT[128 * NN];

__device__ __forceinline__ ull pack2(float x) { ull r; asm("mov.b64 %0, {%1, %1};" : "=l"(r) : "f"(x)); return r; }
__device__ __forceinline__ ull fma2(ull a, ull b, ull c) { ull d; asm("fma.rn.f32x2 %0, %1, %2, %3;" : "=l"(d) : "l"(a), "l"(b), "l"(c)); return d; }
__device__ __forceinline__ float2 unpack2(ull v) { float2 r; asm("mov.b64 {%0, %1}, %2;" : "=f"(r.x), "=f"(r.y) : "l"(v)); return r; }
__device__ __forceinline__ ull dll(double v) { return __double_as_longlong(v); }
__device__ __forceinline__ void cpa16(void* dst, const void* src) {
    unsigned s = (unsigned)__cvta_generic_to_shared(dst);
    asm volatile("cp.async.cg.shared.global [%0], [%1], 16;" ::"r"(s), "l"(src));
}
__device__ __forceinline__ void cpa8(void* dst, const void* src) {
    unsigned s = (unsigned)__cvta_generic_to_shared(dst);
    asm volatile("cp.async.ca.shared.global [%0], [%1], 8;" ::"r"(s), "l"(src));
}
__device__ __forceinline__ unsigned bf2(float lo, float hi) {
    unsigned r; asm("cvt.rn.bf16x2.f32 %0, %1, %2;" : "=r"(r) : "f"(hi), "f"(lo)); return r;
}
__device__ __forceinline__ uint32 smem_u32(const void* p) {
    uint32 a; asm("{ .reg .u64 t; cvta.to.shared.u64 t, %1; cvt.u32.u64 %0, t; }" : "=r"(a) : "l"(p)); return a;
}
#define CPA_COMMIT() asm volatile("cp.async.commit_group;" ::: "memory")
#define CPA_WAIT1() asm volatile("cp.async.wait_group 1;" ::: "memory")
#define CPA_WAIT0() asm volatile("cp.async.wait_group 0;" ::: "memory")

__device__ __forceinline__ void ldmx4(uint32* r, uint32 addr) {
    asm volatile("ldmatrix.sync.aligned.m8n8.x4.shared.b16 {%0,%1,%2,%3}, [%4];"
                 : "=r"(r[0]), "=r"(r[1]), "=r"(r[2]), "=r"(r[3]) : "r"(addr));
}
__device__ __forceinline__ void mma_bf16(float* c, uint32 a0, uint32 a1, uint32 a2, uint32 a3,
                                         uint32 b0, uint32 b1) {
    asm volatile("mma.sync.aligned.m16n8k16.row.col.f32.bf16.bf16.f32 "
                 "{%0,%1,%2,%3},{%4,%5,%6,%7},{%8,%9},{%0,%1,%2,%3};"
                 : "+f"(c[0]), "+f"(c[1]), "+f"(c[2]), "+f"(c[3])
                 : "r"(a0), "r"(a1), "r"(a2), "r"(a3), "r"(b0), "r"(b1));
}

// ---------------- prep ----------------
__global__ __launch_bounds__(256) void k_prep(const float* __restrict__ We1, const float* __restrict__ We2,
                                              const float* __restrict__ Wemb, const float* __restrict__ nodes) {
    int i = blockIdx.x * 256 + threadIdx.x;
    if (i < 65536) { int k = i >> 8, c = i & 255; d_W1T[i] = We1[c * 256 + k]; }
    else if (i < 131072) { int j = i - 65536, k = j >> 8, c = j & 255; d_W2T[j] = We2[c * 256 + k]; }
    else if (i < 163840) { int j = i - 131072, k = j >> 8, c = j & 255; d_WembT[j] = Wemb[c * 128 + k]; }
    else { int j = i - 163840, k = j >> 12, r = j & 4095; d_nodesT[j] = nodes[r * 128 + k]; }
}
__global__ __launch_bounds__(256) void k_adjpack(const int* __restrict__ adj) {
    int wg = (blockIdx.x * 256 + threadIdx.x) >> 5, lane = threadIdx.x & 31;
    unsigned v = (adj[(size_t)wg * 32 + lane] != 0) ? 1u : 0u;
    unsigned word = __ballot_sync(0xFFFFFFFFu, v);
    if (lane == 0) {
        int node = wg >> 7, w = wg & 127;             // w = 0..127 within row
        d_adjT[(size_t)((w >> 1) * NN + node) * 2 + (w & 1)] = word;
    }
}

// ---------------- K1 embed (fp32 g + bf16 gT) ----------------
__global__ __launch_bounds__(256) void k_embed() {
    const int tid = threadIdx.x, bi = blockIdx.x;
    const int fg = tid & 63, ig = tid >> 6;
    const int rowb = bi * 32 + ig * 8, colb = fg * 4;
    ull acc[16];
#pragma unroll
    for (int q = 0; q < 16; q++) acc[q] = 0ull;
#pragma unroll 2
    for (int k = 0; k < 128; k++) {
        double2 wd = *(const double2*)(d_WembT + k * 256 + colb);
        ull w01 = dll(wd.x), w23 = dll(wd.y);
        float4 a0 = *(const float4*)(d_nodesT + (size_t)k * 4096 + rowb);
        float4 a1 = *(const float4*)(d_nodesT + (size_t)k * 4096 + rowb + 4);
        float av[8] = {a0.x, a0.y, a0.z, a0.w, a1.x, a1.y, a1.z, a1.w};
#pragma unroll
        for (int r = 0; r < 8; r++) {
            ull p = pack2(av[r]);
            acc[r * 2] = fma2(p, w01, acc[r * 2]);
            acc[r * 2 + 1] = fma2(p, w23, acc[r * 2 + 1]);
        }
    }
    float z[8][4];
#pragma unroll
    for (int r = 0; r < 8; r++) {
        float2 u0 = unpack2(acc[r * 2]), u1 = unpack2(acc[r * 2 + 1]);
        z[r][0] = u0.x; z[r][1] = u0.y; z[r][2] = u1.x; z[r][3] = u1.y;
        *(float4*)(d_g + (size_t)(rowb + r) * 256 + colb) = make_float4(u0.x, u0.y, u1.x, u1.y);
    }
#pragma unroll
    for (int cc = 0; cc < 4; cc++) {
        uint4 q = make_uint4(bf2(z[0][cc], z[1][cc]), bf2(z[2][cc], z[3][cc]),
                             bf2(z[4][cc], z[5][cc]), bf2(z[6][cc], z[7][cc]));
        *(uint4*)((char*)d_gbfT + ((size_t)(colb + cc) * 4096 + rowb) * 2) = q;
    }
}

// ---------------- K1b scores ----------------
__global__ __launch_bounds__(256) void k_scores(const float* __restrict__ Watt) {
    const int t = blockIdx.x * 256 + threadIdx.x;
    const int node = t >> 2, h = t & 3;
    const float* grow = d_g + (size_t)node * 256 + h * 64;
    float sl = 0.f, sr = 0.f;
#pragma unroll 8
    for (int k = 0; k < 64; k++) {
        float v = grow[k];
        sl += v * __ldg(Watt + k);
        sr += v * __ldg(Watt + 64 + k);
    }
    d_lpack[node * 12 + h] = sl;
    d_lpack[node * 12 + 4 + h] = expf(sl);
    d_lpack[node * 12 + 8 + h] = expf(0.2f * sl);
    d_rp4[node * 4 + h] = make_float4(sr, expf(sr), expf(0.2f * sr), 0.f);
}

// ---------------- K2: HMMA (mma.sync bf16) attention ----------------
// smem bytes: G 2x32768 | RP 2x5120 @65536 | ADJ 2x256 @75776 | DEN 512 @76288 | INV 512 @76800
#define G_OFF 0
#define RP_OFF 65536
#define ADJ_OFF 75776
#define DEN_OFF 76288
#define INV_OFF 76800
#define K2_SMEM 77312

__device__ __forceinline__ void issue_tile(int t, int buf, int tid, int bi, char* sb) {
    // g tile: 256 feat-rows x 64 j (128B/row), SW128-swizzled
    char* Gd = sb + G_OFF + buf * 32768;
    const char* gsrc = (const char*)d_gbfT + (size_t)t * 128;
#pragma unroll
    for (int kk = 0; kk < 8; kk++) {
        int L = tid + kk * 256, row = L >> 3, c = L & 7;
        cpa16(Gd + row * 128 + ((c ^ (row & 7)) << 4), gsrc + (size_t)row * 8192 + c * 16);
    }
    // rp tile: 64 j, padded stride 80B, +h*16
    int j = tid >> 2, h = tid & 3;
    cpa16(sb + RP_OFF + buf * 5120 + j * 80 + h * 16, d_rp4 + t * 256 + tid);
    // adjacency: 32 nodes x 8B
    if (tid < 32)
        cpa8(sb + ADJ_OFF + buf * 256 + tid * 8, d_adjT + (size_t)(t * NN + bi * 32 + tid) * 2);
}

__global__ __launch_bounds__(256, 1) void k_attn() {
    extern __shared__ char sb[];
    const uint32 sb32 = smem_u32(sb);
    const int tid = threadIdx.x, bi = blockIdx.x;
    const int lane = tid & 31, wid = tid >> 5;
    const int h = wid >> 1, nhalf = wid & 1;
    const int fb = h * 64 + nhalf * 32;
    const int i4 = lane >> 2, jq = (lane & 3) << 1;

    // per-thread row params: rows i4 + 8r
    float sl[4], e1[4], e2[4];
#pragma unroll
    for (int r = 0; r < 4; r++) {
        int gi = bi * 32 + i4 + 8 * r;
        sl[r] = d_lpack[gi * 12 + h];
        e1[r] = d_lpack[gi * 12 + 4 + h];
        e2[r] = d_lpack[gi * 12 + 8 + h];
    }
    float C[2][4][4];
#pragma unroll
    for (int m = 0; m < 2; m++)
#pragma unroll
        for (int nf = 0; nf < 4; nf++)
#pragma unroll
            for (int q = 0; q < 4; q++) C[m][nf][q] = 0.f;
    float dsum[4] = {0.f, 0.f, 0.f, 0.f};

    issue_tile(0, 0, tid, bi, sb);
    CPA_COMMIT();

#pragma unroll 1
    for (int t = 0; t < 64; t++) {
        const int buf = t & 1;
        __syncthreads();  // all warps done with buffer buf (tile t-2) -> safe to overwrite
        if (t < 63) { issue_tile(t + 1, buf ^ 1, tid, bi, sb); CPA_COMMIT(); CPA_WAIT1(); }
        else CPA_WAIT0();
        __syncthreads();  // tile t staged

        // ---- B fragments via ldmatrix (k=j, n=f) ----
        uint32 B[4][8];
        {
            const uint32 gb32 = sb32 + G_OFF + buf * 32768;
            const int fr = fb + (lane & 7), c0 = lane >> 3;
#pragma unroll
            for (int nf = 0; nf < 4; nf++) {
                int f = fr + nf * 8;
                uint32 base = gb32 + f * 128;
                ldmx4(&B[nf][0], base + (((c0) ^ (f & 7)) << 4));
                ldmx4(&B[nf][4], base + (((c0 + 4) ^ (f & 7)) << 4));
            }
        }
        // ---- A fragments: masked-exp weights, computed in-register ----
        uint32 A[4][8];
        {
            const uint32* sadj = (const uint32*)(sb + ADJ_OFF + buf * 256);
            uint32 aw[4][2];
#pragma unroll
            for (int r = 0; r < 4; r++) {
                aw[r][0] = sadj[(i4 + 8 * r) * 2];
                aw[r][1] = sadj[(i4 + 8 * r) * 2 + 1];
            }
            const char* rpb = sb + RP_OFF + buf * 5120 + h * 16;
#pragma unroll
            for (int c = 0; c < 8; c++) {
                int j0 = jq + (c << 3);
                float4 p0 = *(const float4*)(rpb + j0 * 80);
                float4 p1 = *(const float4*)(rpb + j0 * 80 + 80);
                int half = c >> 2, sh = j0 & 31;
#pragma unroll
                for (int r = 0; r < 4; r++) {
                    float w0 = (sl[r] + p0.x >= 0.f) ? e1[r] * p0.y : e2[r] * p0.z;
                    float w1 = (sl[r] + p1.x >= 0.f) ? e1[r] * p1.y : e2[r] * p1.z;
                    w0 = ((aw[r][half] >> sh) & 1u) ? w0 : 0.f;
                    w1 = ((aw[r][half] >> (sh + 1)) & 1u) ? w1 : 0.f;
                    dsum[r] += w0 + w1;
                    A[r][c] = bf2(w0, w1);
                }
            }
        }
        // ---- MMA: 2 M-frags x 4 N-frags x 4 K-steps ----
#pragma unroll
        for (int s = 0; s < 4; s++)
#pragma unroll
            for (int nf = 0; nf < 4; nf++) {
                mma_bf16(C[0][nf], A[0][2 * s], A[1][2 * s], A[0][2 * s + 1], A[1][2 * s + 1],
                         B[nf][2 * s], B[nf][2 * s + 1]);
                mma_bf16(C[1][nf], A[2][2 * s], A[3][2 * s], A[2][2 * s + 1], A[3][2 * s + 1],
                         B[nf][2 * s], B[nf][2 * s + 1]);
            }
    }

    // ---- epilogue ----
#pragma unroll
    for (int r = 0; r < 4; r++) {
        dsum[r] += __shfl_xor_sync(0xFFFFFFFFu, dsum[r], 1);
        dsum[r] += __shfl_xor_sync(0xFFFFFFFFu, dsum[r], 2);
    }
    float* den = (float*)(sb + DEN_OFF);
    if (nhalf == 0 && (lane & 3) == 0) {
#pragma unroll
        for (int r = 0; r < 4; r++) den[h * 32 + i4 + 8 * r] = dsum[r];
    }
    __syncthreads();
    float* inv = (float*)(sb + INV_OFF);
    if (tid < 128) inv[tid] = 1.f / den[tid];
    __syncthreads();
    float* sOut = (float*)(sb + G_OFF);  // 32 x 264 fp32 (padded)
#pragma unroll
    for (int m = 0; m < 2; m++)
#pragma unroll
        for (int nf = 0; nf < 4; nf++) {
            int i0 = i4 + 16 * m, f0 = fb + nf * 8 + jq;
            float s0 = inv[h * 32 + i0], s8 = inv[h * 32 + i0 + 8];
            float* q = sOut + i0 * 264 + f0;
            q[0] = C[m][nf][0] * s0; q[1] = C[m][nf][1] * s0;
            float* q8 = sOut + (i0 + 8) * 264 + f0;
            q8[0] = C[m][nf][2] * s8; q8[1] = C[m][nf][3] * s8;
        }
    __syncthreads();
    // coalesced transposed writeback: thread = feature
#pragma unroll
    for (int n4 = 0; n4 < 8; n4++) {
        float4 v;
        v.x = sOut[(n4 * 4 + 0) * 264 + tid];
        v.y = sOut[(n4 * 4 + 1) * 264 + tid];
        v.z = sOut[(n4 * 4 + 2) * 264 + tid];
        v.w = sOut[(n4 * 4 + 3) * 264 + tid];
        *(float4*)(d_hattT + (size_t)tid * 4096 + bi * 32 + n4 * 4) = v;
    }
}

// ---------------- K3: MLP + partial pool ----------------
__global__ __launch_bounds__(256) void k_mlp(const float* __restrict__ b1, const float* __restrict__ b2) {
    __shared__ float sZT[8192];
    __shared__ float sPart[1024];
    const int tid = threadIdx.x, bi = blockIdx.x;
    const int fg = tid & 63, ig = tid >> 6;
    const int rowb = bi * 32 + ig * 8, colb = fg * 4;
    ull acc[16];
#pragma unroll
    for (int q = 0; q < 16; q++) acc[q] = 0ull;
#pragma unroll 2
    for (int k = 0; k < 256; k++) {
        double2 wd = *(const double2*)(d_W1T + k * 256 + colb);
        ull w01 = dll(wd.x), w23 = dll(wd.y);
        float4 a0 = *(const float4*)(d_hattT + (size_t)k * 4096 + rowb);
        float4 a1 = *(const float4*)(d_hattT + (size_t)k * 4096 + rowb + 4);
        float av[8] = {a0.x, a0.y, a0.z, a0.w, a1.x, a1.y, a1.z, a1.w};
#pragma unroll
        for (int r = 0; r < 8; r++) {
            ull p = pack2(av[r]);
            acc[r * 2] = fma2(p, w01, acc[r * 2]);
            acc[r * 2 + 1] = fma2(p, w23, acc[r * 2 + 1]);
        }
    }
    float4 bb = *(const float4*)(b1 + colb);
    float zz[8][4];
#pragma unroll
    for (int r = 0; r < 8; r++) {
        float2 u0 = unpack2(acc[r * 2]), u1 = unpack2(acc[r * 2 + 1]);
        zz[r][0] = fmaxf(u0.x + bb.x, 0.f); zz[r][1] = fmaxf(u0.y + bb.y, 0.f);
        zz[r][2] = fmaxf(u1.x + bb.z, 0.f); zz[r][3] = fmaxf(u1.y + bb.w, 0.f);
    }
#pragma unroll
    for (int cc = 0; cc < 4; cc++) {
        int c = colb + cc, sw = (c >> 2) & 7;
        int blo = (c * 8 + ig * 2) ^ sw, bhi = (c * 8 + ig * 2 + 1) ^ sw;
        *(float4*)(sZT + blo * 4) = make_float4(zz[0][cc], zz[1][cc], zz[2][cc], zz[3][cc]);
        *(float4*)(sZT + bhi * 4) = make_float4(zz[4][cc], zz[5][cc], zz[6][cc], zz[7][cc]);
    }
    __syncthreads();
#pragma unroll
    for (int q = 0; q < 16; q++) acc[q] = 0ull;
#pragma unroll 2
    for (int k = 0; k < 256; k++) {
        double2 wd = *(const double2*)(d_W2T + k * 256 + colb);
        ull w01 = dll(wd.x), w23 = dll(wd.y);
        int sw = (k >> 2) & 7;
        float4 a0 = *(const float4*)(sZT + ((k * 8 + ig * 2) ^ sw) * 4);
        float4 a1 = *(const float4*)(sZT + ((k * 8 + ig * 2 + 1) ^ sw) * 4);
        float av[8] = {a0.x, a0.y, a0.z, a0.w, a1.x, a1.y, a1.z, a1.w};
#pragma unroll
        for (int r = 0; r < 8; r++) {
            ull p = pack2(av[r]);
            acc[r * 2] = fma2(p, w01, acc[r * 2]);
            acc[r * 2 + 1] = fma2(p, w23, acc[r * 2 + 1]);
        }
    }
    float4 b2v = *(const float4*)(b2 + colb);
    float pc0 = 8.f * b2v.x, pc1 = 8.f * b2v.y, pc2 = 8.f * b2v.z, pc3 = 8.f * b2v.w;
#pragma unroll
    for (int r = 0; r < 8; r++) {
        float2 u0 = unpack2(acc[r * 2]), u1 = unpack2(acc[r * 2 + 1]);
        pc0 += u0.x; pc1 += u0.y; pc2 += u1.x; pc3 += u1.y;
    }
    *(float4*)(sPart + ig * 256 + colb) = make_float4(pc0, pc1, pc2, pc3);
    __syncthreads();
    d_part[bi * 256 + tid] = sPart[tid] + sPart[256 + tid] + sPart[512 + tid] + sPart[768 + tid];
}

// ---------------- K4 ----------------
__global__ __launch_bounds__(256) void k_final(const float* __restrict__ Wd1, const float* __restrict__ bd1,
                                               const float* __restrict__ Wd2, const float* __restrict__ bd2,
                                               float* __restrict__ out) {
    __shared__ float pooled[256];
    __shared__ float red[256];
    const int o = threadIdx.x;
    float p = 0.f;
    for (int b = 0; b < 128; b++) p += d_part[b * 256 + o];
    pooled[o] = p;
    __syncthreads();
    float accv = 0.f;
    const float* w = Wd1 + o * 256;
#pragma unroll 4
    for (int k = 0; k < 256; k++) accv += w[k] * pooled[k];
    red[o] = fmaxf(accv + bd1[o], 0.f) * Wd2[o];
    __syncthreads();
    for (int s = 128; s > 0; s >>= 1) {
        if (o < s) red[o] += red[o + s];
        __syncthreads();
    }
    if (o == 0) out[0] = red[0] + bd2[0];
}

extern "C" void kernel_launch(void* const* d_in, const int* in_sizes, int n_in,
                              void* d_out, int out_size) {
    const float* nodes = (const float*)d_in[0];
    const int* adj = (const int*)d_in[1];
    const float* Wemb = (const float*)d_in[2];
    const float* Watt = (const float*)d_in[3];
    const float* We1 = (const float*)d_in[4];
    const float* b1 = (const float*)d_in[5];
    const float* We2 = (const float*)d_in[6];
    const float* b2 = (const float*)d_in[7];
    const float* Wd1 = (const float*)d_in[8];
    const float* bd1 = (const float*)d_in[9];
    const float* Wd2 = (const float*)d_in[10];
    const float* bd2 = (const float*)d_in[11];
    float* out = (float*)d_out;

    cudaFuncSetAttribute(k_attn, cudaFuncAttributeMaxDynamicSharedMemorySize, K2_SMEM);

    k_prep<<<2688, 256>>>(We1, We2, Wemb, nodes);
    k_adjpack<<<65536, 256>>>(adj);
    k_embed<<<128, 256>>>();
    k_scores<<<64, 256>>>(Watt);
    k_attn<<<128, 256, K2_SMEM>>>();
    k_mlp<<<128, 256>>>(b1, b2);
    k_final<<<1, 256>>>(Wd1, bd1, Wd2, bd2, out);
}

// round 7
// speedup vs baseline: 2.4326x; 1.0663x over previous
#include <cuda_runtime.h>
#include <cstdint>
#include <cstddef>

#define NN 4096
typedef unsigned long long ull;
typedef unsigned int uint32;

__device__ unsigned short d_gbfT[256 * NN];  // bf16 g transposed [feat][node]
__device__ float d_lpack[NN * 12];
__device__ float4 d_rp4[NN * 4];             // {sr, exp(sr), exp(.2sr), 0}
__device__ unsigned d_adjT[128 * NN * 2];    // adjacency bits, tile-major
__device__ float d_hattT[256 * NN];
__device__ float d_part[128 * 256];
__device__ float d_W1T[256 * 256];
__device__ float d_W2T[256 * 256];
__device__ float d_WembT[128 * 256];
__device__ float d_nodesT[128 * NN];

__device__ __forceinline__ ull pack2(float x) { ull r; asm("mov.b64 %0, {%1, %1};" : "=l"(r) : "f"(x)); return r; }
__device__ __forceinline__ ull fma2(ull a, ull b, ull c) { ull d; asm("fma.rn.f32x2 %0, %1, %2, %3;" : "=l"(d) : "l"(a), "l"(b), "l"(c)); return d; }
__device__ __forceinline__ float2 unpack2(ull v) { float2 r; asm("mov.b64 {%0, %1}, %2;" : "=f"(r.x), "=f"(r.y) : "l"(v)); return r; }
__device__ __forceinline__ ull dll(double v) { return __double_as_longlong(v); }
__device__ __forceinline__ void cpa16(void* dst, const void* src) {
    unsigned s = (unsigned)__cvta_generic_to_shared(dst);
    asm volatile("cp.async.cg.shared.global [%0], [%1], 16;" ::"r"(s), "l"(src));
}
__device__ __forceinline__ void cpa8(void* dst, const void* src) {
    unsigned s = (unsigned)__cvta_generic_to_shared(dst);
    asm volatile("cp.async.ca.shared.global [%0], [%1], 8;" ::"r"(s), "l"(src));
}
__device__ __forceinline__ unsigned bf2(float lo, float hi) {
    unsigned r; asm("cvt.rn.bf16x2.f32 %0, %1, %2;" : "=r"(r) : "f"(hi), "f"(lo)); return r;
}
__device__ __forceinline__ uint32 smem_u32(const void* p) {
    uint32 a; asm("{ .reg .u64 t; cvta.to.shared.u64 t, %1; cvt.u32.u64 %0, t; }" : "=r"(a) : "l"(p)); return a;
}
#define CPA_COMMIT() asm volatile("cp.async.commit_group;" ::: "memory")
#define CPA_WAIT1() asm volatile("cp.async.wait_group 1;" ::: "memory")
#define CPA_WAIT0() asm volatile("cp.async.wait_group 0;" ::: "memory")

__device__ __forceinline__ void ldmx4(uint32* r, uint32 addr) {
    asm volatile("ldmatrix.sync.aligned.m8n8.x4.shared.b16 {%0,%1,%2,%3}, [%4];"
                 : "=r"(r[0]), "=r"(r[1]), "=r"(r[2]), "=r"(r[3]) : "r"(addr));
}
__device__ __forceinline__ void mma_bf16(float* c, uint32 a0, uint32 a1, uint32 a2, uint32 a3,
                                         uint32 b0, uint32 b1) {
    asm volatile("mma.sync.aligned.m16n8k16.row.col.f32.bf16.bf16.f32 "
                 "{%0,%1,%2,%3},{%4,%5,%6,%7},{%8,%9},{%0,%1,%2,%3};"
                 : "+f"(c[0]), "+f"(c[1]), "+f"(c[2]), "+f"(c[3])
                 : "r"(a0), "r"(a1), "r"(a2), "r"(a3), "r"(b0), "r"(b1));
}

// ---------------- prep: weight transposes ----------------
__global__ __launch_bounds__(256) void k_prep(const float* __restrict__ We1, const float* __restrict__ We2,
                                              const float* __restrict__ Wemb) {
    int i = blockIdx.x * 256 + threadIdx.x;  // 163840
    if (i < 65536) { int k = i >> 8, c = i & 255; d_W1T[i] = We1[c * 256 + k]; }
    else if (i < 131072) { int j = i - 65536, k = j >> 8, c = j & 255; d_W2T[j] = We2[c * 256 + k]; }
    else { int j = i - 131072, k = j >> 8, c = j & 255; d_WembT[j] = Wemb[c * 128 + k]; }
}
// tiled transpose of nodes [4096,128] -> nodesT [128,4096]
__global__ void k_tnodes(const float* __restrict__ nodes) {
    __shared__ float tile[32][33];
    const int bx = blockIdx.x, by = blockIdx.y, tx = threadIdx.x, ty = threadIdx.y;
#pragma unroll
    for (int q = 0; q < 4; q++)
        tile[ty + 8 * q][tx] = nodes[(size_t)(bx * 32 + ty + 8 * q) * 128 + by * 32 + tx];
    __syncthreads();
#pragma unroll
    for (int q = 0; q < 4; q++)
        d_nodesT[(size_t)(by * 32 + ty + 8 * q) * 4096 + bx * 32 + tx] = tile[tx][ty + 8 * q];
}
__global__ __launch_bounds__(256) void k_adjpack(const int* __restrict__ adj) {
    int wg = (blockIdx.x * 256 + threadIdx.x) >> 5, lane = threadIdx.x & 31;
    unsigned v = (adj[(size_t)wg * 32 + lane] != 0) ? 1u : 0u;
    unsigned word = __ballot_sync(0xFFFFFFFFu, v);
    if (lane == 0) {
        int node = wg >> 7, w = wg & 127;
        d_adjT[(size_t)((w >> 1) * NN + node) * 2 + (w & 1)] = word;
    }
}

// ---------------- K1: embed + fused score packs ----------------
__global__ __launch_bounds__(256) void k_embed(const float* __restrict__ Watt) {
    __shared__ float sRed[4096];
    const int tid = threadIdx.x, bi = blockIdx.x;
    const int fg = tid & 63, ig = tid >> 6;
    const int rowb = bi * 32 + ig * 8, colb = fg * 4;
    ull acc[16];
#pragma unroll
    for (int q = 0; q < 16; q++) acc[q] = 0ull;
#pragma unroll 2
    for (int k = 0; k < 128; k++) {
        double2 wd = *(const double2*)(d_WembT + k * 256 + colb);
        ull w01 = dll(wd.x), w23 = dll(wd.y);
        float4 a0 = *(const float4*)(d_nodesT + (size_t)k * 4096 + rowb);
        float4 a1 = *(const float4*)(d_nodesT + (size_t)k * 4096 + rowb + 4);
        float av[8] = {a0.x, a0.y, a0.z, a0.w, a1.x, a1.y, a1.z, a1.w};
#pragma unroll
        for (int r = 0; r < 8; r++) {
            ull p = pack2(av[r]);
            acc[r * 2] = fma2(p, w01, acc[r * 2]);
            acc[r * 2 + 1] = fma2(p, w23, acc[r * 2 + 1]);
        }
    }
    float z[8][4];
#pragma unroll
    for (int r = 0; r < 8; r++) {
        float2 u0 = unpack2(acc[r * 2]), u1 = unpack2(acc[r * 2 + 1]);
        z[r][0] = u0.x; z[r][1] = u0.y; z[r][2] = u1.x; z[r][3] = u1.y;
    }
#pragma unroll
    for (int cc = 0; cc < 4; cc++) {
        uint4 q = make_uint4(bf2(z[0][cc], z[1][cc]), bf2(z[2][cc], z[3][cc]),
                             bf2(z[4][cc], z[5][cc]), bf2(z[6][cc], z[7][cc]));
        *(uint4*)((char*)d_gbfT + ((size_t)(colb + cc) * 4096 + rowb) * 2) = q;
    }
    // fused attention-score partials
    const int h = fg >> 4, fi = fg & 15;
    float4 al = *(const float4*)(Watt + (colb & 63));
    float4 ar = *(const float4*)(Watt + 64 + (colb & 63));
#pragma unroll
    for (int r = 0; r < 8; r++) {
        float slp = z[r][0] * al.x + z[r][1] * al.y + z[r][2] * al.z + z[r][3] * al.w;
        float srp = z[r][0] * ar.x + z[r][1] * ar.y + z[r][2] * ar.z + z[r][3] * ar.w;
        int ri = ig * 8 + r;
        sRed[((ri * 4 + h) * 2 + 0) * 16 + fi] = slp;
        sRed[((ri * 4 + h) * 2 + 1) * 16 + fi] = srp;
    }
    __syncthreads();
    if (tid < 128) {
        int ri = tid >> 2, hh = tid & 3;
        float sl = 0.f, sr = 0.f;
#pragma unroll
        for (int q = 0; q < 16; q++) {
            sl += sRed[((ri * 4 + hh) * 2 + 0) * 16 + q];
            sr += sRed[((ri * 4 + hh) * 2 + 1) * 16 + q];
        }
        int gi = bi * 32 + ri;
        d_lpack[gi * 12 + hh] = sl;
        d_lpack[gi * 12 + 4 + hh] = expf(sl);
        d_lpack[gi * 12 + 8 + hh] = expf(0.2f * sl);
        d_rp4[gi * 4 + hh] = make_float4(sr, expf(sr), expf(0.2f * sr), 0.f);
    }
}

// ---------------- K2: HMMA attention (M-split, triple-buffered) ----------------
#define G_OFF 0
#define RP_OFF 98304
#define ADJ_OFF 113664
#define DEN_OFF 114432
#define INV_OFF 114944
#define K2_SMEM 115456

__device__ __forceinline__ void issue_tile(int t, int slot, int tid, int bi, char* sb) {
    char* Gd = sb + G_OFF + slot * 32768;
    const char* gsrc = (const char*)d_gbfT + (size_t)t * 128;
#pragma unroll
    for (int kk = 0; kk < 8; kk++) {
        int L = tid + kk * 256, row = L >> 3, c = L & 7;
        cpa16(Gd + row * 128 + ((c ^ (row & 7)) << 4), gsrc + (size_t)row * 8192 + c * 16);
    }
    int j = tid >> 2, hh = tid & 3;
    cpa16(sb + RP_OFF + slot * 5120 + j * 80 + hh * 16, d_rp4 + t * 256 + tid);
    if (tid < 32)
        cpa8(sb + ADJ_OFF + slot * 256 + tid * 8, d_adjT + (size_t)(t * NN + bi * 32 + tid) * 2);
}

__global__ __launch_bounds__(256, 1) void k_attn() {
    extern __shared__ char sb[];
    const uint32 sb32 = smem_u32(sb);
    const int tid = threadIdx.x, bi = blockIdx.x;
    const int lane = tid & 31, wid = tid >> 5;
    const int h = wid >> 1, mh = wid & 1;
    const int i4 = lane >> 2, jq = (lane & 3) << 1;
    const int r0 = mh * 16 + i4;  // warp owns rows r0, r0+8; all 64 f of head h

    float sl[2], e1[2], e2[2];
#pragma unroll
    for (int r = 0; r < 2; r++) {
        int gi = bi * 32 + r0 + 8 * r;
        sl[r] = d_lpack[gi * 12 + h];
        e1[r] = d_lpack[gi * 12 + 4 + h];
        e2[r] = d_lpack[gi * 12 + 8 + h];
    }
    float C[8][4];
#pragma unroll
    for (int nf = 0; nf < 8; nf++)
#pragma unroll
        for (int q = 0; q < 4; q++) C[nf][q] = 0.f;
    float dsum[2] = {0.f, 0.f};

    issue_tile(0, 0, tid, bi, sb); CPA_COMMIT();
    issue_tile(1, 1, tid, bi, sb); CPA_COMMIT();

#pragma unroll 1
    for (int t = 0; t < 64; t++) {
        if (t < 63) CPA_WAIT1(); else CPA_WAIT0();
        __syncthreads();  // tile t visible everywhere; all warps past compute(t-1)
        if (t + 2 < 64) { issue_tile(t + 2, (t + 2) % 3, tid, bi, sb); CPA_COMMIT(); }
        const int slot = t % 3;

        // B fragments: 8 n-frags covering 64 f of this head
        uint32 B[8][8];
        {
            const uint32 gb32 = sb32 + G_OFF + slot * 32768;
            const int fr = h * 64 + (lane & 7), c0 = lane >> 3;
#pragma unroll
            for (int nf = 0; nf < 8; nf++) {
                int f = fr + nf * 8;
                uint32 base = gb32 + f * 128;
                ldmx4(&B[nf][0], base + ((c0 ^ (f & 7)) << 4));
                ldmx4(&B[nf][4], base + (((c0 + 4) ^ (f & 7)) << 4));
            }
        }
        // A fragments: masked-exp weights for 2 row-octets
        uint32 A[2][8];
        {
            const uint32* sadj = (const uint32*)(sb + ADJ_OFF + slot * 256);
            uint32 aw[2][2];
#pragma unroll
            for (int r = 0; r < 2; r++) {
                aw[r][0] = sadj[(r0 + 8 * r) * 2];
                aw[r][1] = sadj[(r0 + 8 * r) * 2 + 1];
            }
            const char* rpb = sb + RP_OFF + slot * 5120 + h * 16;
#pragma unroll
            for (int c = 0; c < 8; c++) {
                int j0 = jq + (c << 3);
                float4 p0 = *(const float4*)(rpb + j0 * 80);
                float4 p1 = *(const float4*)(rpb + j0 * 80 + 80);
                int half = c >> 2, sh = j0 & 31;
#pragma unroll
                for (int r = 0; r < 2; r++) {
                    float w0 = (sl[r] + p0.x >= 0.f) ? e1[r] * p0.y : e2[r] * p0.z;
                    float w1 = (sl[r] + p1.x >= 0.f) ? e1[r] * p1.y : e2[r] * p1.z;
                    w0 = ((aw[r][half] >> sh) & 1u) ? w0 : 0.f;
                    w1 = ((aw[r][half] >> (sh + 1)) & 1u) ? w1 : 0.f;
                    dsum[r] += w0 + w1;
                    A[r][c] = bf2(w0, w1);
                }
            }
        }
#pragma unroll
        for (int s = 0; s < 4; s++)
#pragma unroll
            for (int nf = 0; nf < 8; nf++)
                mma_bf16(C[nf], A[0][2 * s], A[1][2 * s], A[0][2 * s + 1], A[1][2 * s + 1],
                         B[nf][2 * s], B[nf][2 * s + 1]);
    }

    // epilogue
#pragma unroll
    for (int r = 0; r < 2; r++) {
        dsum[r] += __shfl_xor_sync(0xFFFFFFFFu, dsum[r], 1);
        dsum[r] += __shfl_xor_sync(0xFFFFFFFFu, dsum[r], 2);
    }
    float* den = (float*)(sb + DEN_OFF);
    if ((lane & 3) == 0) {
        den[h * 32 + r0] = dsum[0];
        den[h * 32 + r0 + 8] = dsum[1];
    }
    __syncthreads();
    float* inv = (float*)(sb + INV_OFF);
    if (tid < 128) inv[tid] = 1.f / den[tid];
    __syncthreads();
    float* sOut = (float*)(sb + G_OFF);  // 32 x 264 fp32
    {
        float s0 = inv[h * 32 + r0], s8 = inv[h * 32 + r0 + 8];
#pragma unroll
        for (int nf = 0; nf < 8; nf++) {
            int f0 = h * 64 + nf * 8 + jq;
            float* q = sOut + r0 * 264 + f0;
            q[0] = C[nf][0] * s0; q[1] = C[nf][1] * s0;
            float* q8 = sOut + (r0 + 8) * 264 + f0;
            q8[0] = C[nf][2] * s8; q8[1] = C[nf][3] * s8;
        }
    }
    __syncthreads();
#pragma unroll
    for (int n4 = 0; n4 < 8; n4++) {
        float4 v;
        v.x = sOut[(n4 * 4 + 0) * 264 + tid];
        v.y = sOut[(n4 * 4 + 1) * 264 + tid];
        v.z = sOut[(n4 * 4 + 2) * 264 + tid];
        v.w = sOut[(n4 * 4 + 3) * 264 + tid];
        *(float4*)(d_hattT + (size_t)tid * 4096 + bi * 32 + n4 * 4) = v;
    }
}

// ---------------- K3: MLP + partial pool ----------------
__global__ __launch_bounds__(256) void k_mlp(const float* __restrict__ b1, const float* __restrict__ b2) {
    __shared__ float sZT[8192];
    __shared__ float sPart[1024];
    const int tid = threadIdx.x, bi = blockIdx.x;
    const int fg = tid & 63, ig = tid >> 6;
    const int rowb = bi * 32 + ig * 8, colb = fg * 4;
    ull acc[16];
#pragma unroll
    for (int q = 0; q < 16; q++) acc[q] = 0ull;
#pragma unroll 2
    for (int k = 0; k < 256; k++) {
        double2 wd = *(const double2*)(d_W1T + k * 256 + colb);
        ull w01 = dll(wd.x), w23 = dll(wd.y);
        float4 a0 = *(const float4*)(d_hattT + (size_t)k * 4096 + rowb);
        float4 a1 = *(const float4*)(d_hattT + (size_t)k * 4096 + rowb + 4);
        float av[8] = {a0.x, a0.y, a0.z, a0.w, a1.x, a1.y, a1.z, a1.w};
#pragma unroll
        for (int r = 0; r < 8; r++) {
            ull p = pack2(av[r]);
            acc[r * 2] = fma2(p, w01, acc[r * 2]);
            acc[r * 2 + 1] = fma2(p, w23, acc[r * 2 + 1]);
        }
    }
    float4 bb = *(const float4*)(b1 + colb);
    float zz[8][4];
#pragma unroll
    for (int r = 0; r < 8; r++) {
        float2 u0 = unpack2(acc[r * 2]), u1 = unpack2(acc[r * 2 + 1]);
        zz[r][0] = fmaxf(u0.x + bb.x, 0.f); zz[r][1] = fmaxf(u0.y + bb.y, 0.f);
        zz[r][2] = fmaxf(u1.x + bb.z, 0.f); zz[r][3] = fmaxf(u1.y + bb.w, 0.f);
    }
#pragma unroll
    for (int cc = 0; cc < 4; cc++) {
        int c = colb + cc, sw = (c >> 2) & 7;
        int blo = (c * 8 + ig * 2) ^ sw, bhi = (c * 8 + ig * 2 + 1) ^ sw;
        *(float4*)(sZT + blo * 4) = make_float4(zz[0][cc], zz[1][cc], zz[2][cc], zz[3][cc]);
        *(float4*)(sZT + bhi * 4) = make_float4(zz[4][cc], zz[5][cc], zz[6][cc], zz[7][cc]);
    }
    __syncthreads();
#pragma unroll
    for (int q = 0; q < 16; q++) acc[q] = 0ull;
#pragma unroll 2
    for (int k = 0; k < 256; k++) {
        double2 wd = *(const double2*)(d_W2T + k * 256 + colb);
        ull w01 = dll(wd.x), w23 = dll(wd.y);
        int sw = (k >> 2) & 7;
        float4 a0 = *(const float4*)(sZT + ((k * 8 + ig * 2) ^ sw) * 4);
        float4 a1 = *(const float4*)(sZT + ((k * 8 + ig * 2 + 1) ^ sw) * 4);
        float av[8] = {a0.x, a0.y, a0.z, a0.w, a1.x, a1.y, a1.z, a1.w};
#pragma unroll
        for (int r = 0; r < 8; r++) {
            ull p = pack2(av[r]);
            acc[r * 2] = fma2(p, w01, acc[r * 2]);
            acc[r * 2 + 1] = fma2(p, w23, acc[r * 2 + 1]);
        }
    }
    float4 b2v = *(const float4*)(b2 + colb);
    float pc0 = 8.f * b2v.x, pc1 = 8.f * b2v.y, pc2 = 8.f * b2v.z, pc3 = 8.f * b2v.w;
#pragma unroll
    for (int r = 0; r < 8; r++) {
        float2 u0 = unpack2(acc[r * 2]), u1 = unpack2(acc[r * 2 + 1]);
        pc0 += u0.x; pc1 += u0.y; pc2 += u1.x; pc3 += u1.y;
    }
    *(float4*)(sPart + ig * 256 + colb) = make_float4(pc0, pc1, pc2, pc3);
    __syncthreads();
    d_part[bi * 256 + tid] = sPart[tid] + sPart[256 + tid] + sPart[512 + tid] + sPart[768 + tid];
}

// ---------------- K4 ----------------
__global__ __launch_bounds__(256) void k_final(const float* __restrict__ Wd1, const float* __restrict__ bd1,
                                               const float* __restrict__ Wd2, const float* __restrict__ bd2,
                                               float* __restrict__ out) {
    __shared__ float pooled[256];
    __shared__ float red[256];
    const int o = threadIdx.x;
    float p = 0.f;
    for (int b = 0; b < 128; b++) p += d_part[b * 256 + o];
    pooled[o] = p;
    __syncthreads();
    float accv = 0.f;
    const float* w = Wd1 + o * 256;
#pragma unroll 4
    for (int k = 0; k < 256; k++) accv += w[k] * pooled[k];
    red[o] = fmaxf(accv + bd1[o], 0.f) * Wd2[o];
    __syncthreads();
    for (int s = 128; s > 0; s >>= 1) {
        if (o < s) red[o] += red[o + s];
        __syncthreads();
    }
    if (o == 0) out[0] = red[0] + bd2[0];
}

extern "C" void kernel_launch(void* const* d_in, const int* in_sizes, int n_in,
                              void* d_out, int out_size) {
    const float* nodes = (const float*)d_in[0];
    const int* adj = (const int*)d_in[1];
    const float* Wemb = (const float*)d_in[2];
    const float* Watt = (const float*)d_in[3];
    const float* We1 = (const float*)d_in[4];
    const float* b1 = (const float*)d_in[5];
    const float* We2 = (const float*)d_in[6];
    const float* b2 = (const float*)d_in[7];
    const float* Wd1 = (const float*)d_in[8];
    const float* bd1 = (const float*)d_in[9];
    const float* Wd2 = (const float*)d_in[10];
    const float* bd2 = (const float*)d_in[11];
    float* out = (float*)d_out;

    cudaFuncSetAttribute(k_attn, cudaFuncAttributeMaxDynamicSharedMemorySize, K2_SMEM);

    k_prep<<<640, 256>>>(We1, We2, Wemb);
    k_tnodes<<<dim3(128, 4), dim3(32, 8)>>>(nodes);
    k_adjpack<<<65536, 256>>>(adj);
    k_embed<<<128, 256>>>(Watt);
    k_attn<<<128, 256, K2_SMEM>>>();
    k_mlp<<<128, 256>>>(b1, b2);
    k_final<<<1, 256>>>(Wd1, bd1, Wd2, bd2, out);
}

// round 8
// speedup vs baseline: 3.5128x; 1.4441x over previous
#include <cuda_runtime.h>
#include <cstdint>
#include <cstddef>

#define NN 4096
typedef unsigned long long ull;
typedef unsigned int uint32;

__device__ unsigned short d_gbfT[256 * NN];  // bf16 g transposed [feat][node]
__device__ float d_lpack[NN * 12];
__device__ float4 d_rp4[NN * 4];             // {sr, exp(sr), exp(.2sr), 0}
__device__ unsigned d_adjT[128 * NN * 2];    // adjacency bits, tile-major
__device__ float d_hattT[256 * NN];
__device__ float d_part[128 * 256];
__device__ float d_W1T[256 * 256];
__device__ float d_W2T[256 * 256];
__device__ float d_WembT[128 * 256];
__device__ float d_nodesT[128 * NN];

__device__ __forceinline__ ull pack2(float x) { ull r; asm("mov.b64 %0, {%1, %1};" : "=l"(r) : "f"(x)); return r; }
__device__ __forceinline__ ull fma2(ull a, ull b, ull c) { ull d; asm("fma.rn.f32x2 %0, %1, %2, %3;" : "=l"(d) : "l"(a), "l"(b), "l"(c)); return d; }
__device__ __forceinline__ float2 unpack2(ull v) { float2 r; asm("mov.b64 {%0, %1}, %2;" : "=f"(r.x), "=f"(r.y) : "l"(v)); return r; }
__device__ __forceinline__ ull dll(double v) { return __double_as_longlong(v); }
__device__ __forceinline__ void cpa16(void* dst, const void* src) {
    unsigned s = (unsigned)__cvta_generic_to_shared(dst);
    asm volatile("cp.async.cg.shared.global [%0], [%1], 16;" ::"r"(s), "l"(src));
}
__device__ __forceinline__ void cpa8(void* dst, const void* src) {
    unsigned s = (unsigned)__cvta_generic_to_shared(dst);
    asm volatile("cp.async.ca.shared.global [%0], [%1], 8;" ::"r"(s), "l"(src));
}
__device__ __forceinline__ unsigned bf2(float lo, float hi) {
    unsigned r; asm("cvt.rn.bf16x2.f32 %0, %1, %2;" : "=r"(r) : "f"(hi), "f"(lo)); return r;
}
__device__ __forceinline__ uint32 smem_u32(const void* p) {
    uint32 a; asm("{ .reg .u64 t; cvta.to.shared.u64 t, %1; cvt.u32.u64 %0, t; }" : "=r"(a) : "l"(p)); return a;
}
#define CPA_COMMIT() asm volatile("cp.async.commit_group;" ::: "memory")
#define CPA_WAIT1() asm volatile("cp.async.wait_group 1;" ::: "memory")
#define CPA_WAIT0() asm volatile("cp.async.wait_group 0;" ::: "memory")

__device__ __forceinline__ void ldmx4(uint32* r, uint32 addr) {
    asm volatile("ldmatrix.sync.aligned.m8n8.x4.shared.b16 {%0,%1,%2,%3}, [%4];"
                 : "=r"(r[0]), "=r"(r[1]), "=r"(r[2]), "=r"(r[3]) : "r"(addr));
}
__device__ __forceinline__ void mma_bf16(float* c, uint32 a0, uint32 a1, uint32 a2, uint32 a3,
                                         uint32 b0, uint32 b1) {
    asm volatile("mma.sync.aligned.m16n8k16.row.col.f32.bf16.bf16.f32 "
                 "{%0,%1,%2,%3},{%4,%5,%6,%7},{%8,%9},{%0,%1,%2,%3};"
                 : "+f"(c[0]), "+f"(c[1]), "+f"(c[2]), "+f"(c[3])
                 : "r"(a0), "r"(a1), "r"(a2), "r"(a3), "r"(b0), "r"(b1));
}

// ---------------- prep: weight transposes ----------------
__global__ __launch_bounds__(256) void k_prep(const float* __restrict__ We1, const float* __restrict__ We2,
                                              const float* __restrict__ Wemb) {
    int i = blockIdx.x * 256 + threadIdx.x;  // 163840
    if (i < 65536) { int k = i >> 8, c = i & 255; d_W1T[i] = We1[c * 256 + k]; }
    else if (i < 131072) { int j = i - 65536, k = j >> 8, c = j & 255; d_W2T[j] = We2[c * 256 + k]; }
    else { int j = i - 131072, k = j >> 8, c = j & 255; d_WembT[j] = Wemb[c * 128 + k]; }
}
__global__ void k_tnodes(const float* __restrict__ nodes) {
    __shared__ float tile[32][33];
    const int bx = blockIdx.x, by = blockIdx.y, tx = threadIdx.x, ty = threadIdx.y;
#pragma unroll
    for (int q = 0; q < 4; q++)
        tile[ty + 8 * q][tx] = nodes[(size_t)(bx * 32 + ty + 8 * q) * 128 + by * 32 + tx];
    __syncthreads();
#pragma unroll
    for (int q = 0; q < 4; q++)
        d_nodesT[(size_t)(by * 32 + ty + 8 * q) * 4096 + bx * 32 + tx] = tile[tx][ty + 8 * q];
}
__global__ __launch_bounds__(256) void k_adjpack(const int* __restrict__ adj) {
    int wg = (blockIdx.x * 256 + threadIdx.x) >> 5, lane = threadIdx.x & 31;
    unsigned v = (adj[(size_t)wg * 32 + lane] != 0) ? 1u : 0u;
    unsigned word = __ballot_sync(0xFFFFFFFFu, v);
    if (lane == 0) {
        int node = wg >> 7, w = wg & 127;
        d_adjT[(size_t)((w >> 1) * NN + node) * 2 + (w & 1)] = word;
    }
}

// ---------------- K1: embed + fused score packs (smem-staged, prefetched) ----------------
__global__ __launch_bounds__(256) void k_embed(const float* __restrict__ Watt) {
    __shared__ float sA[128 * 32];   // [k][row] 16KB
    __shared__ float sRed[4096];
    const int tid = threadIdx.x, bi = blockIdx.x;
    // stage node tile: 128 k-rows x 32 floats
#pragma unroll
    for (int c = 0; c < 4; c++) {
        int L = tid + c * 256, k = L >> 3, q = L & 7;
        cpa16(sA + k * 32 + q * 4, d_nodesT + (size_t)k * 4096 + bi * 32 + q * 4);
    }
    CPA_COMMIT(); CPA_WAIT0();
    __syncthreads();

    const int fg = tid & 63, ig = tid >> 6;
    const int rowb = bi * 32 + ig * 8, colb = fg * 4;
    ull acc[16];
#pragma unroll
    for (int q = 0; q < 16; q++) acc[q] = 0ull;
#pragma unroll 1
    for (int k0 = 0; k0 < 128; k0 += 8) {
        ull w01[8], w23[8];
#pragma unroll
        for (int u = 0; u < 8; u++) {
            double2 wd = *(const double2*)(d_WembT + (k0 + u) * 256 + colb);
            w01[u] = dll(wd.x); w23[u] = dll(wd.y);
        }
#pragma unroll
        for (int u = 0; u < 8; u++) {
            const float* ar = sA + (k0 + u) * 32 + ig * 8;
#pragma unroll
            for (int r = 0; r < 8; r++) {
                ull p = pack2(ar[r]);
                acc[r * 2] = fma2(p, w01[u], acc[r * 2]);
                acc[r * 2 + 1] = fma2(p, w23[u], acc[r * 2 + 1]);
            }
        }
    }
    float z[8][4];
#pragma unroll
    for (int r = 0; r < 8; r++) {
        float2 u0 = unpack2(acc[r * 2]), u1 = unpack2(acc[r * 2 + 1]);
        z[r][0] = u0.x; z[r][1] = u0.y; z[r][2] = u1.x; z[r][3] = u1.y;
    }
#pragma unroll
    for (int cc = 0; cc < 4; cc++) {
        uint4 q = make_uint4(bf2(z[0][cc], z[1][cc]), bf2(z[2][cc], z[3][cc]),
                             bf2(z[4][cc], z[5][cc]), bf2(z[6][cc], z[7][cc]));
        *(uint4*)((char*)d_gbfT + ((size_t)(colb + cc) * 4096 + rowb) * 2) = q;
    }
    // fused attention-score partials
    const int h = fg >> 4, fi = fg & 15;
    float4 al = *(const float4*)(Watt + (colb & 63));
    float4 ar4 = *(const float4*)(Watt + 64 + (colb & 63));
#pragma unroll
    for (int r = 0; r < 8; r++) {
        float slp = z[r][0] * al.x + z[r][1] * al.y + z[r][2] * al.z + z[r][3] * al.w;
        float srp = z[r][0] * ar4.x + z[r][1] * ar4.y + z[r][2] * ar4.z + z[r][3] * ar4.w;
        int ri = ig * 8 + r;
        sRed[((ri * 4 + h) * 2 + 0) * 16 + fi] = slp;
        sRed[((ri * 4 + h) * 2 + 1) * 16 + fi] = srp;
    }
    __syncthreads();
    if (tid < 128) {
        int ri = tid >> 2, hh = tid & 3;
        float sl = 0.f, sr = 0.f;
#pragma unroll
        for (int q = 0; q < 16; q++) {
            sl += sRed[((ri * 4 + hh) * 2 + 0) * 16 + q];
            sr += sRed[((ri * 4 + hh) * 2 + 1) * 16 + q];
        }
        int gi = bi * 32 + ri;
        d_lpack[gi * 12 + hh] = sl;
        d_lpack[gi * 12 + 4 + hh] = expf(sl);
        d_lpack[gi * 12 + 8 + hh] = expf(0.2f * sl);
        d_rp4[gi * 4 + hh] = make_float4(sr, expf(sr), expf(0.2f * sr), 0.f);
    }
}

// ---------------- K2: HMMA attention (unchanged from R7) ----------------
#define G_OFF 0
#define RP_OFF 98304
#define ADJ_OFF 113664
#define DEN_OFF 114432
#define INV_OFF 114944
#define K2_SMEM 115456

__device__ __forceinline__ void issue_tile(int t, int slot, int tid, int bi, char* sb) {
    char* Gd = sb + G_OFF + slot * 32768;
    const char* gsrc = (const char*)d_gbfT + (size_t)t * 128;
#pragma unroll
    for (int kk = 0; kk < 8; kk++) {
        int L = tid + kk * 256, row = L >> 3, c = L & 7;
        cpa16(Gd + row * 128 + ((c ^ (row & 7)) << 4), gsrc + (size_t)row * 8192 + c * 16);
    }
    int j = tid >> 2, hh = tid & 3;
    cpa16(sb + RP_OFF + slot * 5120 + j * 80 + hh * 16, d_rp4 + t * 256 + tid);
    if (tid < 32)
        cpa8(sb + ADJ_OFF + slot * 256 + tid * 8, d_adjT + (size_t)(t * NN + bi * 32 + tid) * 2);
}

__global__ __launch_bounds__(256, 1) void k_attn() {
    extern __shared__ char sb[];
    const uint32 sb32 = smem_u32(sb);
    const int tid = threadIdx.x, bi = blockIdx.x;
    const int lane = tid & 31, wid = tid >> 5;
    const int h = wid >> 1, mh = wid & 1;
    const int i4 = lane >> 2, jq = (lane & 3) << 1;
    const int r0 = mh * 16 + i4;

    float sl[2], e1[2], e2[2];
#pragma unroll
    for (int r = 0; r < 2; r++) {
        int gi = bi * 32 + r0 + 8 * r;
        sl[r] = d_lpack[gi * 12 + h];
        e1[r] = d_lpack[gi * 12 + 4 + h];
        e2[r] = d_lpack[gi * 12 + 8 + h];
    }
    float C[8][4];
#pragma unroll
    for (int nf = 0; nf < 8; nf++)
#pragma unroll
        for (int q = 0; q < 4; q++) C[nf][q] = 0.f;
    float dsum[2] = {0.f, 0.f};

    issue_tile(0, 0, tid, bi, sb); CPA_COMMIT();
    issue_tile(1, 1, tid, bi, sb); CPA_COMMIT();

#pragma unroll 1
    for (int t = 0; t < 64; t++) {
        if (t < 63) CPA_WAIT1(); else CPA_WAIT0();
        __syncthreads();
        if (t + 2 < 64) { issue_tile(t + 2, (t + 2) % 3, tid, bi, sb); CPA_COMMIT(); }
        const int slot = t % 3;

        uint32 B[8][8];
        {
            const uint32 gb32 = sb32 + G_OFF + slot * 32768;
            const int fr = h * 64 + (lane & 7), c0 = lane >> 3;
#pragma unroll
            for (int nf = 0; nf < 8; nf++) {
                int f = fr + nf * 8;
                uint32 base = gb32 + f * 128;
                ldmx4(&B[nf][0], base + ((c0 ^ (f & 7)) << 4));
                ldmx4(&B[nf][4], base + (((c0 + 4) ^ (f & 7)) << 4));
            }
        }
        uint32 A[2][8];
        {
            const uint32* sadj = (const uint32*)(sb + ADJ_OFF + slot * 256);
            uint32 aw[2][2];
#pragma unroll
            for (int r = 0; r < 2; r++) {
                aw[r][0] = sadj[(r0 + 8 * r) * 2];
                aw[r][1] = sadj[(r0 + 8 * r) * 2 + 1];
            }
            const char* rpb = sb + RP_OFF + slot * 5120 + h * 16;
#pragma unroll
            for (int c = 0; c < 8; c++) {
                int j0 = jq + (c << 3);
                float4 p0 = *(const float4*)(rpb + j0 * 80);
                float4 p1 = *(const float4*)(rpb + j0 * 80 + 80);
                int half = c >> 2, sh = j0 & 31;
#pragma unroll
                for (int r = 0; r < 2; r++) {
                    float w0 = (sl[r] + p0.x >= 0.f) ? e1[r] * p0.y : e2[r] * p0.z;
                    float w1 = (sl[r] + p1.x >= 0.f) ? e1[r] * p1.y : e2[r] * p1.z;
                    w0 = ((aw[r][half] >> sh) & 1u) ? w0 : 0.f;
                    w1 = ((aw[r][half] >> (sh + 1)) & 1u) ? w1 : 0.f;
                    dsum[r] += w0 + w1;
                    A[r][c] = bf2(w0, w1);
                }
            }
        }
#pragma unroll
        for (int s = 0; s < 4; s++)
#pragma unroll
            for (int nf = 0; nf < 8; nf++)
                mma_bf16(C[nf], A[0][2 * s], A[1][2 * s], A[0][2 * s + 1], A[1][2 * s + 1],
                         B[nf][2 * s], B[nf][2 * s + 1]);
    }

#pragma unroll
    for (int r = 0; r < 2; r++) {
        dsum[r] += __shfl_xor_sync(0xFFFFFFFFu, dsum[r], 1);
        dsum[r] += __shfl_xor_sync(0xFFFFFFFFu, dsum[r], 2);
    }
    float* den = (float*)(sb + DEN_OFF);
    if ((lane & 3) == 0) {
        den[h * 32 + r0] = dsum[0];
        den[h * 32 + r0 + 8] = dsum[1];
    }
    __syncthreads();
    float* inv = (float*)(sb + INV_OFF);
    if (tid < 128) inv[tid] = 1.f / den[tid];
    __syncthreads();
    float* sOut = (float*)(sb + G_OFF);
    {
        float s0 = inv[h * 32 + r0], s8 = inv[h * 32 + r0 + 8];
#pragma unroll
        for (int nf = 0; nf < 8; nf++) {
            int f0 = h * 64 + nf * 8 + jq;
            float* q = sOut + r0 * 264 + f0;
            q[0] = C[nf][0] * s0; q[1] = C[nf][1] * s0;
            float* q8 = sOut + (r0 + 8) * 264 + f0;
            q8[0] = C[nf][2] * s8; q8[1] = C[nf][3] * s8;
        }
    }
    __syncthreads();
#pragma unroll
    for (int n4 = 0; n4 < 8; n4++) {
        float4 v;
        v.x = sOut[(n4 * 4 + 0) * 264 + tid];
        v.y = sOut[(n4 * 4 + 1) * 264 + tid];
        v.z = sOut[(n4 * 4 + 2) * 264 + tid];
        v.w = sOut[(n4 * 4 + 3) * 264 + tid];
        *(float4*)(d_hattT + (size_t)tid * 4096 + bi * 32 + n4 * 4) = v;
    }
}

// ---------------- K3: MLP + partial pool (smem-staged, prefetched) ----------------
// dynamic smem: 256*33 floats (33792B). Phase 1 uses [k*32+row]; phase 2 relaid [k*33+row].
__global__ __launch_bounds__(256) void k_mlp(const float* __restrict__ b1, const float* __restrict__ b2) {
    extern __shared__ float sm[];
    __shared__ float sPart[1024];
    const int tid = threadIdx.x, bi = blockIdx.x;
    const int fg = tid & 63, ig = tid >> 6;
    const int colb = fg * 4;

    // stage Hatt tile: 256 k-rows x 32 floats
#pragma unroll
    for (int c = 0; c < 8; c++) {
        int L = tid + c * 256, k = L >> 3, q = L & 7;
        cpa16(sm + k * 32 + q * 4, d_hattT + (size_t)k * 4096 + bi * 32 + q * 4);
    }
    CPA_COMMIT(); CPA_WAIT0();
    __syncthreads();

    ull acc[16];
#pragma unroll
    for (int q = 0; q < 16; q++) acc[q] = 0ull;
#pragma unroll 1
    for (int k0 = 0; k0 < 256; k0 += 8) {
        ull w01[8], w23[8];
#pragma unroll
        for (int u = 0; u < 8; u++) {
            double2 wd = *(const double2*)(d_W1T + (k0 + u) * 256 + colb);
            w01[u] = dll(wd.x); w23[u] = dll(wd.y);
        }
#pragma unroll
        for (int u = 0; u < 8; u++) {
            const float* ar = sm + (k0 + u) * 32 + ig * 8;
#pragma unroll
            for (int r = 0; r < 8; r++) {
                ull p = pack2(ar[r]);
                acc[r * 2] = fma2(p, w01[u], acc[r * 2]);
                acc[r * 2 + 1] = fma2(p, w23[u], acc[r * 2 + 1]);
            }
        }
    }
    float4 bb = *(const float4*)(b1 + colb);
    float zz[8][4];
#pragma unroll
    for (int r = 0; r < 8; r++) {
        float2 u0 = unpack2(acc[r * 2]), u1 = unpack2(acc[r * 2 + 1]);
        zz[r][0] = fmaxf(u0.x + bb.x, 0.f); zz[r][1] = fmaxf(u0.y + bb.y, 0.f);
        zz[r][2] = fmaxf(u1.x + bb.z, 0.f); zz[r][3] = fmaxf(u1.y + bb.w, 0.f);
    }
    __syncthreads();  // done reading phase-1 layout
    // re-lay layer-1 output: [hid k][row], stride 33
#pragma unroll
    for (int cc = 0; cc < 4; cc++)
#pragma unroll
        for (int r = 0; r < 8; r++)
            sm[(colb + cc) * 33 + ig * 8 + r] = zz[r][cc];
    __syncthreads();

#pragma unroll
    for (int q = 0; q < 16; q++) acc[q] = 0ull;
#pragma unroll 1
    for (int k0 = 0; k0 < 256; k0 += 8) {
        ull w01[8], w23[8];
#pragma unroll
        for (int u = 0; u < 8; u++) {
            double2 wd = *(const double2*)(d_W2T + (k0 + u) * 256 + colb);
            w01[u] = dll(wd.x); w23[u] = dll(wd.y);
        }
#pragma unroll
        for (int u = 0; u < 8; u++) {
            const float* ar = sm + (k0 + u) * 33 + ig * 8;
#pragma unroll
            for (int r = 0; r < 8; r++) {
                ull p = pack2(ar[r]);
                acc[r * 2] = fma2(p, w01[u], acc[r * 2]);
                acc[r * 2 + 1] = fma2(p, w23[u], acc[r * 2 + 1]);
            }
        }
    }
    float4 b2v = *(const float4*)(b2 + colb);
    float pc0 = 8.f * b2v.x, pc1 = 8.f * b2v.y, pc2 = 8.f * b2v.z, pc3 = 8.f * b2v.w;
#pragma unroll
    for (int r = 0; r < 8; r++) {
        float2 u0 = unpack2(acc[r * 2]), u1 = unpack2(acc[r * 2 + 1]);
        pc0 += u0.x; pc1 += u0.y; pc2 += u1.x; pc3 += u1.y;
    }
    *(float4*)(sPart + ig * 256 + colb) = make_float4(pc0, pc1, pc2, pc3);
    __syncthreads();
    d_part[bi * 256 + tid] = sPart[tid] + sPart[256 + tid] + sPart[512 + tid] + sPart[768 + tid];
}

// ---------------- K4 ----------------
__global__ __launch_bounds__(256) void k_final(const float* __restrict__ Wd1, const float* __restrict__ bd1,
                                               const float* __restrict__ Wd2, const float* __restrict__ bd2,
                                               float* __restrict__ out) {
    __shared__ float pooled[256];
    __shared__ float red[256];
    const int o = threadIdx.x;
    float p = 0.f;
    for (int b = 0; b < 128; b++) p += d_part[b * 256 + o];
    pooled[o] = p;
    __syncthreads();
    float accv = 0.f;
    const float* w = Wd1 + o * 256;
#pragma unroll 4
    for (int k = 0; k < 256; k++) accv += w[k] * pooled[k];
    red[o] = fmaxf(accv + bd1[o], 0.f) * Wd2[o];
    __syncthreads();
    for (int s = 128; s > 0; s >>= 1) {
        if (o < s) red[o] += red[o + s];
        __syncthreads();
    }
    if (o == 0) out[0] = red[0] + bd2[0];
}

extern "C" void kernel_launch(void* const* d_in, const int* in_sizes, int n_in,
                              void* d_out, int out_size) {
    const float* nodes = (const float*)d_in[0];
    const int* adj = (const int*)d_in[1];
    const float* Wemb = (const float*)d_in[2];
    const float* Watt = (const float*)d_in[3];
    const float* We1 = (const float*)d_in[4];
    const float* b1 = (const float*)d_in[5];
    const float* We2 = (const float*)d_in[6];
    const float* b2 = (const float*)d_in[7];
    const float* Wd1 = (const float*)d_in[8];
    const float* bd1 = (const float*)d_in[9];
    const float* Wd2 = (const float*)d_in[10];
    const float* bd2 = (const float*)d_in[11];
    float* out = (float*)d_out;

    cudaFuncSetAttribute(k_attn, cudaFuncAttributeMaxDynamicSharedMemorySize, K2_SMEM);

    k_prep<<<640, 256>>>(We1, We2, Wemb);
    k_tnodes<<<dim3(128, 4), dim3(32, 8)>>>(nodes);
    k_adjpack<<<65536, 256>>>(adj);
    k_embed<<<128, 256>>>(Watt);
    k_attn<<<128, 256, K2_SMEM>>>();
    k_mlp<<<128, 256, 33792>>>(b1, b2);
    k_final<<<1, 256>>>(Wd1, bd1, Wd2, bd2, out);
}